// round 2
// baseline (speedup 1.0000x reference)
#include <cuda_runtime.h>
#include <math.h>

// Problem constants
#define D_MODEL 1024
#define NH      16
#define DK      64
#define BATCH   4
#define TSEQ    2048
#define BT      (BATCH * TSEQ)      // 8192 rows
#define C3      (3 * D_MODEL)       // 3072

// Scratch (allocation-free rule: __device__ globals)
__device__ float g_qkv[BT * C3];        // 96 MB: [8192][3072]  (Q|K|V)
__device__ float g_y[BT * D_MODEL];     // 32 MB: [8192][1024]  attention output

// ---------------------------------------------------------------------------
// SGEMM (NT): C[m][n] = sum_k A[m][k] * B[n][k] + bias[n]
// A: [M][K] row-major, B: [N][K] row-major (i.e. torch Linear weight)
// 128x128 block tile, BK=8, 256 threads, 8x8 per-thread tile.
// ---------------------------------------------------------------------------
__global__ __launch_bounds__(256) void sgemm_nt_bias(
    const float* __restrict__ A, const float* __restrict__ B,
    const float* __restrict__ bias, float* __restrict__ C,
    int M, int N, int K)
{
    __shared__ float As[8][128];
    __shared__ float Bs[8][128];

    const int tid = threadIdx.x;
    const int tx  = tid & 15;     // 0..15 -> n direction
    const int ty  = tid >> 4;     // 0..15 -> m direction
    const int bm  = blockIdx.y * 128;
    const int bn  = blockIdx.x * 128;

    // global load mapping: each thread loads one float4 of A and one of B per K-step
    const int lrow = tid >> 1;         // 0..127
    const int lcol = (tid & 1) * 4;    // 0 or 4

    const float* Ag = A + (size_t)(bm + lrow) * K + lcol;
    const float* Bg = B + (size_t)(bn + lrow) * K + lcol;

    float acc[8][8];
#pragma unroll
    for (int i = 0; i < 8; i++)
#pragma unroll
        for (int j = 0; j < 8; j++) acc[i][j] = 0.f;

    for (int k0 = 0; k0 < K; k0 += 8) {
        float4 a4 = *(const float4*)(Ag + k0);
        float4 b4 = *(const float4*)(Bg + k0);
        __syncthreads();   // previous tile's compute done before overwrite
        As[lcol + 0][lrow] = a4.x;
        As[lcol + 1][lrow] = a4.y;
        As[lcol + 2][lrow] = a4.z;
        As[lcol + 3][lrow] = a4.w;
        Bs[lcol + 0][lrow] = b4.x;
        Bs[lcol + 1][lrow] = b4.y;
        Bs[lcol + 2][lrow] = b4.z;
        Bs[lcol + 3][lrow] = b4.w;
        __syncthreads();

#pragma unroll
        for (int kk = 0; kk < 8; kk++) {
            float ar[8], br[8];
            *(float4*)&ar[0] = *(const float4*)&As[kk][ty * 4];
            *(float4*)&ar[4] = *(const float4*)&As[kk][64 + ty * 4];
            *(float4*)&br[0] = *(const float4*)&Bs[kk][tx * 4];
            *(float4*)&br[4] = *(const float4*)&Bs[kk][64 + tx * 4];
#pragma unroll
            for (int i = 0; i < 8; i++)
#pragma unroll
                for (int j = 0; j < 8; j++)
                    acc[i][j] += ar[i] * br[j];
        }
    }

    // epilogue (vectorized stores; cols in two groups of 4)
    const int n0 = bn + tx * 4;
    const int n1 = bn + 64 + tx * 4;
    float4 bia0 = *(const float4*)&bias[n0];
    float4 bia1 = *(const float4*)&bias[n1];
#pragma unroll
    for (int i = 0; i < 8; i++) {
        int mi = bm + ((i < 4) ? (ty * 4 + i) : (64 + ty * 4 + i - 4));
        float4 v0, v1;
        v0.x = acc[i][0] + bia0.x; v0.y = acc[i][1] + bia0.y;
        v0.z = acc[i][2] + bia0.z; v0.w = acc[i][3] + bia0.w;
        v1.x = acc[i][4] + bia1.x; v1.y = acc[i][5] + bia1.y;
        v1.z = acc[i][6] + bia1.z; v1.w = acc[i][7] + bia1.w;
        *(float4*)&C[(size_t)mi * N + n0] = v0;
        *(float4*)&C[(size_t)mi * N + n1] = v1;
    }
}

// ---------------------------------------------------------------------------
// Flash attention (fp32, causal). One CTA = 64 query rows for one (b,h).
// Iterates key blocks of 64 (only kb <= qblk), online softmax.
// qkv layout: [8192][3072], Q at col h*64, K at 1024+h*64, V at 2048+h*64.
// ---------------------------------------------------------------------------
#define FS 68          // padded smem row stride (floats)
#define FLASH_SMEM (4 * 64 * FS * sizeof(float))   // Qs,Ks,Vs,Ps = 69632 B

__global__ __launch_bounds__(256) void flash_attn_kernel(
    const float* __restrict__ qkv, float* __restrict__ y)
{
    extern __shared__ float sm[];
    float* Qs = sm;             // [d][r]  (transposed)
    float* Ks = Qs + 64 * FS;   // [d][c]  (transposed)
    float* Vs = Ks + 64 * FS;   // [c][dv] (natural)
    float* Ps = Vs + 64 * FS;   // [r][c]  (natural)

    const int tid  = threadIdx.x;
    const int tx   = tid & 15;   // key-col / dv direction
    const int ty   = tid >> 4;   // query-row direction
    const int qblk = blockIdx.x;             // 0..31
    const int b    = blockIdx.y >> 4;        // 0..3
    const int h    = blockIdx.y & 15;        // 0..15

    const float* base = qkv + (size_t)b * TSEQ * C3 + h * DK;

    // load Q tile transposed: 64 rows x 64 d  (each thread: 16 floats)
    {
        const int lrow = tid >> 2;          // 0..63  (query row in tile)
        const int lcol = (tid & 3) * 16;    // d offset: 0,16,32,48
        const float* qg = base + (size_t)(qblk * 64 + lrow) * C3 + lcol;
#pragma unroll
        for (int u = 0; u < 16; u += 4) {
            float4 v = *(const float4*)(qg + u);
            Qs[(lcol + u + 0) * FS + lrow] = v.x;
            Qs[(lcol + u + 1) * FS + lrow] = v.y;
            Qs[(lcol + u + 2) * FS + lrow] = v.z;
            Qs[(lcol + u + 3) * FS + lrow] = v.w;
        }
    }

    float m_prev[4], l[4], o[4][4];
#pragma unroll
    for (int i = 0; i < 4; i++) {
        m_prev[i] = -1e30f;
        l[i] = 0.f;
#pragma unroll
        for (int j = 0; j < 4; j++) o[i][j] = 0.f;
    }

    const int lrow = tid >> 2;
    const int lcol = (tid & 3) * 16;

    for (int kb = 0; kb <= qblk; kb++) {
        // load K (transposed) and V (natural) tiles
        const float* kg = base + D_MODEL     + (size_t)(kb * 64 + lrow) * C3 + lcol;
        const float* vg = base + 2 * D_MODEL + (size_t)(kb * 64 + lrow) * C3 + lcol;
        __syncthreads();   // previous PV + Q-load visible / done
#pragma unroll
        for (int u = 0; u < 16; u += 4) {
            float4 kv = *(const float4*)(kg + u);
            Ks[(lcol + u + 0) * FS + lrow] = kv.x;
            Ks[(lcol + u + 1) * FS + lrow] = kv.y;
            Ks[(lcol + u + 2) * FS + lrow] = kv.z;
            Ks[(lcol + u + 3) * FS + lrow] = kv.w;
            float4 vv = *(const float4*)(vg + u);
            *(float4*)&Vs[lrow * FS + lcol + u] = vv;
        }
        __syncthreads();

        // S = Q @ K^T  (4x4 per-thread tile)
        float s[4][4];
#pragma unroll
        for (int i = 0; i < 4; i++)
#pragma unroll
            for (int j = 0; j < 4; j++) s[i][j] = 0.f;

#pragma unroll 4
        for (int d = 0; d < 64; d++) {
            float4 qf = *(const float4*)&Qs[d * FS + ty * 4];
            float4 kf = *(const float4*)&Ks[d * FS + tx * 4];
            float qa[4] = {qf.x, qf.y, qf.z, qf.w};
            float ka[4] = {kf.x, kf.y, kf.z, kf.w};
#pragma unroll
            for (int i = 0; i < 4; i++)
#pragma unroll
                for (int j = 0; j < 4; j++)
                    s[i][j] += qa[i] * ka[j];
        }

        // scale + causal mask (only diagonal block needs masking)
        const float scale = 0.125f;   // 1/sqrt(64)
#pragma unroll
        for (int i = 0; i < 4; i++)
#pragma unroll
            for (int j = 0; j < 4; j++) s[i][j] *= scale;

        if (kb == qblk) {
            // local row index r = ty*4+i, local col c = tx*4+j; mask c > r
#pragma unroll
            for (int i = 0; i < 4; i++) {
                int r = ty * 4 + i;
#pragma unroll
                for (int j = 0; j < 4; j++) {
                    int c = tx * 4 + j;
                    if (c > r) s[i][j] = -1e30f;
                }
            }
        }

        // online softmax
        float p[4][4], rs[4];
#pragma unroll
        for (int i = 0; i < 4; i++) {
            float rm = fmaxf(fmaxf(s[i][0], s[i][1]), fmaxf(s[i][2], s[i][3]));
#pragma unroll
            for (int off = 1; off < 16; off <<= 1)
                rm = fmaxf(rm, __shfl_xor_sync(0xffffffffu, rm, off));
            float new_m = fmaxf(m_prev[i], rm);
            float alpha = __expf(m_prev[i] - new_m);
            float sum = 0.f;
#pragma unroll
            for (int j = 0; j < 4; j++) {
                p[i][j] = __expf(s[i][j] - new_m);
                sum += p[i][j];
            }
#pragma unroll
            for (int off = 1; off < 16; off <<= 1)
                sum += __shfl_xor_sync(0xffffffffu, sum, off);
            l[i] = l[i] * alpha + sum;
            m_prev[i] = new_m;
#pragma unroll
            for (int j = 0; j < 4; j++) o[i][j] *= alpha;
            rs[i] = sum; (void)rs;
        }

        // write P to smem (natural layout), then PV
#pragma unroll
        for (int i = 0; i < 4; i++) {
            float4 pv = make_float4(p[i][0], p[i][1], p[i][2], p[i][3]);
            *(float4*)&Ps[(ty * 4 + i) * FS + tx * 4] = pv;
        }
        __syncthreads();

#pragma unroll 2
        for (int c0 = 0; c0 < 64; c0 += 4) {
            float pa[4][4], va[4][4];
#pragma unroll
            for (int i = 0; i < 4; i++) {
                float4 pf = *(const float4*)&Ps[(ty * 4 + i) * FS + c0];
                pa[i][0] = pf.x; pa[i][1] = pf.y; pa[i][2] = pf.z; pa[i][3] = pf.w;
            }
#pragma unroll
            for (int cc = 0; cc < 4; cc++) {
                float4 vf = *(const float4*)&Vs[(c0 + cc) * FS + tx * 4];
                va[cc][0] = vf.x; va[cc][1] = vf.y; va[cc][2] = vf.z; va[cc][3] = vf.w;
            }
#pragma unroll
            for (int i = 0; i < 4; i++)
#pragma unroll
                for (int cc = 0; cc < 4; cc++)
#pragma unroll
                    for (int j = 0; j < 4; j++)
                        o[i][j] += pa[i][cc] * va[cc][j];
        }
    }

    // finalize and write y[b*T + qblk*64 + r][h*64 + dv]
#pragma unroll
    for (int i = 0; i < 4; i++) {
        float inv = 1.f / l[i];
        int row = b * TSEQ + qblk * 64 + ty * 4 + i;
        int col = h * DK + tx * 4;
        float4 v = make_float4(o[i][0] * inv, o[i][1] * inv,
                               o[i][2] * inv, o[i][3] * inv);
        *(float4*)&y[(size_t)row * D_MODEL + col] = v;
    }
}

// ---------------------------------------------------------------------------
// launch
// ---------------------------------------------------------------------------
extern "C" void kernel_launch(void* const* d_in, const int* in_sizes, int n_in,
                              void* d_out, int out_size)
{
    const float* x      = (const float*)d_in[0];
    const float* W_attn = (const float*)d_in[1];
    const float* b_attn = (const float*)d_in[2];
    const float* W_o    = (const float*)d_in[3];
    const float* b_o    = (const float*)d_in[4];
    float* out = (float*)d_out;

    float* qkv = nullptr;
    float* yb  = nullptr;
    cudaGetSymbolAddress((void**)&qkv, g_qkv);
    cudaGetSymbolAddress((void**)&yb,  g_y);

    // 1) QKV projection: [8192,1024] @ [3072,1024]^T + b -> [8192,3072]
    sgemm_nt_bias<<<dim3(C3 / 128, BT / 128), 256>>>(
        x, W_attn, b_attn, qkv, BT, C3, D_MODEL);

    // 2) causal flash attention -> g_y [8192,1024]
    cudaFuncSetAttribute(flash_attn_kernel,
                         cudaFuncAttributeMaxDynamicSharedMemorySize,
                         (int)FLASH_SMEM);
    flash_attn_kernel<<<dim3(TSEQ / 64, BATCH * NH), 256, FLASH_SMEM>>>(qkv, yb);

    // 3) output projection: [8192,1024] @ [1024,1024]^T + b -> out
    sgemm_nt_bias<<<dim3(D_MODEL / 128, BT / 128), 256>>>(
        yb, W_o, b_o, out, BT, D_MODEL, D_MODEL);
}

// round 5
// speedup vs baseline: 2.2493x; 2.2493x over previous
#include <cuda_runtime.h>
#include <math.h>
#include <stdint.h>

// Problem constants
#define D_MODEL 1024
#define NH      16
#define DK      64
#define BATCH   4
#define TSEQ    2048
#define BT      (BATCH * TSEQ)      // 8192 rows
#define C3      (3 * D_MODEL)       // 3072

// Scratch (allocation-free rule: __device__ globals)
__device__ float g_qkv[BT * C3];        // 96 MB: [8192][3072]  (Q|K|V)
__device__ float g_y[BT * D_MODEL];     // 32 MB: [8192][1024]  attention output

// ---------------------------------------------------------------------------
// tf32 helpers
// ---------------------------------------------------------------------------
__device__ __forceinline__ uint32_t f2tf(float f) {
    uint32_t r;
    asm("cvt.rna.tf32.f32 %0, %1;" : "=r"(r) : "f"(f));
    return r;
}

__device__ __forceinline__ void mma8(float c[4], const uint32_t a[4], const uint32_t b[2]) {
    asm volatile(
        "mma.sync.aligned.m16n8k8.row.col.f32.tf32.tf32.f32 "
        "{%0,%1,%2,%3},{%4,%5,%6,%7},{%8,%9},{%0,%1,%2,%3};"
        : "+f"(c[0]), "+f"(c[1]), "+f"(c[2]), "+f"(c[3])
        : "r"(a[0]), "r"(a[1]), "r"(a[2]), "r"(a[3]), "r"(b[0]), "r"(b[1]));
}

// ---------------------------------------------------------------------------
// TF32 tensor-core SGEMM (NT): C[m][n] = sum_k A[m][k]*B[n][k] + bias[n]
// 128x128 tile, BK=16, 256 threads = 8 warps (2m x 4n), warp = 64x32.
// ---------------------------------------------------------------------------
#define SK 136   // smem k-row stride; 136 % 32 == 8 -> frag reads hit 32 distinct banks

__global__ __launch_bounds__(256) void sgemm_tf32_bias(
    const float* __restrict__ A, const float* __restrict__ B,
    const float* __restrict__ bias, float* __restrict__ C,
    int M, int N, int K)
{
    __shared__ uint32_t As[16][SK];   // [k][m] tf32 bits
    __shared__ uint32_t Bs[16][SK];   // [k][n] tf32 bits

    const int tid  = threadIdx.x;
    const int warp = tid >> 5;
    const int lane = tid & 31;
    const int gid  = lane >> 2;
    const int tig  = lane & 3;
    const int wm   = warp >> 2;   // 0..1
    const int wn   = warp & 3;    // 0..3
    const int bm   = blockIdx.y * 128;
    const int bn   = blockIdx.x * 128;

    const int lrow = tid >> 1;         // 0..127
    const int lk   = (tid & 1) * 8;    // 0 or 8

    const float* Ag = A + (size_t)(bm + lrow) * K + lk;
    const float* Bg = B + (size_t)(bn + lrow) * K + lk;

    float acc[4][4][4];
#pragma unroll
    for (int i = 0; i < 4; i++)
#pragma unroll
        for (int j = 0; j < 4; j++)
#pragma unroll
            for (int e = 0; e < 4; e++) acc[i][j][e] = 0.f;

    float4 pa0 = *(const float4*)(Ag);
    float4 pa1 = *(const float4*)(Ag + 4);
    float4 pb0 = *(const float4*)(Bg);
    float4 pb1 = *(const float4*)(Bg + 4);

    for (int k0 = 0; k0 < K; k0 += 16) {
        __syncthreads();
        As[lk + 0][lrow] = f2tf(pa0.x); As[lk + 1][lrow] = f2tf(pa0.y);
        As[lk + 2][lrow] = f2tf(pa0.z); As[lk + 3][lrow] = f2tf(pa0.w);
        As[lk + 4][lrow] = f2tf(pa1.x); As[lk + 5][lrow] = f2tf(pa1.y);
        As[lk + 6][lrow] = f2tf(pa1.z); As[lk + 7][lrow] = f2tf(pa1.w);
        Bs[lk + 0][lrow] = f2tf(pb0.x); Bs[lk + 1][lrow] = f2tf(pb0.y);
        Bs[lk + 2][lrow] = f2tf(pb0.z); Bs[lk + 3][lrow] = f2tf(pb0.w);
        Bs[lk + 4][lrow] = f2tf(pb1.x); Bs[lk + 5][lrow] = f2tf(pb1.y);
        Bs[lk + 6][lrow] = f2tf(pb1.z); Bs[lk + 7][lrow] = f2tf(pb1.w);
        __syncthreads();

        if (k0 + 16 < K) {
            pa0 = *(const float4*)(Ag + k0 + 16);
            pa1 = *(const float4*)(Ag + k0 + 20);
            pb0 = *(const float4*)(Bg + k0 + 16);
            pb1 = *(const float4*)(Bg + k0 + 20);
        }

#pragma unroll
        for (int ks = 0; ks < 16; ks += 8) {
            uint32_t af[4][4], bf[4][2];
#pragma unroll
            for (int mt = 0; mt < 4; mt++) {
                int m = wm * 64 + mt * 16;
                af[mt][0] = As[ks + tig][m + gid];
                af[mt][1] = As[ks + tig][m + gid + 8];
                af[mt][2] = As[ks + tig + 4][m + gid];
                af[mt][3] = As[ks + tig + 4][m + gid + 8];
            }
#pragma unroll
            for (int nt = 0; nt < 4; nt++) {
                int n = wn * 32 + nt * 8;
                bf[nt][0] = Bs[ks + tig][n + gid];
                bf[nt][1] = Bs[ks + tig + 4][n + gid];
            }
#pragma unroll
            for (int mt = 0; mt < 4; mt++)
#pragma unroll
                for (int nt = 0; nt < 4; nt++)
                    mma8(acc[mt][nt], af[mt], bf[nt]);
        }
    }

    // epilogue
#pragma unroll
    for (int mt = 0; mt < 4; mt++) {
        int r0 = bm + wm * 64 + mt * 16 + gid;
#pragma unroll
        for (int nt = 0; nt < 4; nt++) {
            int c = bn + wn * 32 + nt * 8 + tig * 2;
            float2 b2 = *(const float2*)&bias[c];
            float2 v0 = make_float2(acc[mt][nt][0] + b2.x, acc[mt][nt][1] + b2.y);
            float2 v1 = make_float2(acc[mt][nt][2] + b2.x, acc[mt][nt][3] + b2.y);
            *(float2*)&C[(size_t)r0 * N + c]       = v0;
            *(float2*)&C[(size_t)(r0 + 8) * N + c] = v1;
        }
    }
}

// ---------------------------------------------------------------------------
// TF32 flash attention (causal). CTA = 128 query rows of one (b,h).
// 8 warps, warp = 16 query rows x all 64 key cols -> warp-local softmax.
// ---------------------------------------------------------------------------
#define PQS 68   // Ps/Q stride: (4*gid+tig)%32 covers 32 banks -> conflict-free A-frags
#define KVS 72   // Ks/Vs stride: 72%32==8 -> tig offsets 0,8,16,24 -> conflict-free B-frags

#define FLASH_SMEM_U32 (2 * 64 * KVS + 128 * PQS)   // Ks + Vs + Ps
#define FLASH_SMEM_B   (FLASH_SMEM_U32 * 4)          // 71680 bytes

__global__ __launch_bounds__(256) void flash_attn_tf32(
    const float* __restrict__ qkv, float* __restrict__ y)
{
    extern __shared__ uint32_t sm[];
    uint32_t* Ks = sm;                 // [d=64][kv=64]
    uint32_t* Vs = Ks + 64 * KVS;      // [kv=64][dv=64]
    uint32_t* Ps = Vs + 64 * KVS;      // [q=128][kv=64]  (also Q staging)

    const int tid  = threadIdx.x;
    const int warp = tid >> 5;
    const int lane = tid & 31;
    const int gid  = lane >> 2;
    const int tig  = lane & 3;

    const int qblk = (gridDim.x - 1) - blockIdx.x;   // big blocks first
    const int b    = blockIdx.y >> 4;
    const int h    = blockIdx.y & 15;

    const float* base = qkv + (size_t)b * TSEQ * C3 + h * DK;
    const int m0g = qblk * 128;

    // ---- stage Q into Ps natural [128][64], then load per-warp A-fragments
    {
        const int lrow = tid >> 1;
        const int lc   = (tid & 1) * 32;
        const float* qg = base + (size_t)(m0g + lrow) * C3 + lc;
#pragma unroll
        for (int u = 0; u < 32; u += 4) {
            float4 v = *(const float4*)(qg + u);
            Ps[lrow * PQS + lc + u + 0] = f2tf(v.x);
            Ps[lrow * PQS + lc + u + 1] = f2tf(v.y);
            Ps[lrow * PQS + lc + u + 2] = f2tf(v.z);
            Ps[lrow * PQS + lc + u + 3] = f2tf(v.w);
        }
    }
    __syncthreads();

    uint32_t qf[8][4];
    {
        const int mr = warp * 16;
#pragma unroll
        for (int kt = 0; kt < 8; kt++) {
            qf[kt][0] = Ps[(mr + gid) * PQS + kt * 8 + tig];
            qf[kt][1] = Ps[(mr + gid + 8) * PQS + kt * 8 + tig];
            qf[kt][2] = Ps[(mr + gid) * PQS + kt * 8 + tig + 4];
            qf[kt][3] = Ps[(mr + gid + 8) * PQS + kt * 8 + tig + 4];
        }
    }

    float o[8][4];
#pragma unroll
    for (int nt = 0; nt < 8; nt++)
#pragma unroll
        for (int e = 0; e < 4; e++) o[nt][e] = 0.f;
    float mx0 = -1e30f, mx1 = -1e30f, l0 = 0.f, l1 = 0.f;

    const int rglob0 = m0g + warp * 16 + gid;
    const int rglob1 = rglob0 + 8;
    const int nkb = 2 * qblk + 2;

    const int krow = tid >> 2;          // 0..63
    const int kc   = (tid & 3) * 16;

    for (int kb = 0; kb < nkb; kb++) {
        __syncthreads();   // frag loads / previous PV finished with Ks,Vs,Ps

        // load K (transposed [d][kv]) and V (natural [kv][dv])
        const float* kg = base + D_MODEL     + (size_t)(kb * 64 + krow) * C3 + kc;
        const float* vg = base + 2 * D_MODEL + (size_t)(kb * 64 + krow) * C3 + kc;
#pragma unroll
        for (int u = 0; u < 16; u += 4) {
            float4 kv4 = *(const float4*)(kg + u);
            Ks[(kc + u + 0) * KVS + krow] = f2tf(kv4.x);
            Ks[(kc + u + 1) * KVS + krow] = f2tf(kv4.y);
            Ks[(kc + u + 2) * KVS + krow] = f2tf(kv4.z);
            Ks[(kc + u + 3) * KVS + krow] = f2tf(kv4.w);
            float4 vv4 = *(const float4*)(vg + u);
            Vs[krow * KVS + kc + u + 0] = f2tf(vv4.x);
            Vs[krow * KVS + kc + u + 1] = f2tf(vv4.y);
            Vs[krow * KVS + kc + u + 2] = f2tf(vv4.z);
            Vs[krow * KVS + kc + u + 3] = f2tf(vv4.w);
        }
        __syncthreads();

        // ---- S = Q @ K^T   (warp: 16 rows x 64 cols)
        float s[8][4];
#pragma unroll
        for (int nt = 0; nt < 8; nt++)
#pragma unroll
            for (int e = 0; e < 4; e++) s[nt][e] = 0.f;

#pragma unroll
        for (int kt = 0; kt < 8; kt++) {
#pragma unroll
            for (int nt = 0; nt < 8; nt++) {
                uint32_t bf[2];
                bf[0] = Ks[(kt * 8 + tig) * KVS + nt * 8 + gid];
                bf[1] = Ks[(kt * 8 + tig + 4) * KVS + nt * 8 + gid];
                mma8(s[nt], qf[kt], bf);
            }
        }

        // ---- scale + causal mask
        const float scale = 0.125f;
        if (kb >= 2 * qblk) {
#pragma unroll
            for (int nt = 0; nt < 8; nt++) {
                int c0 = kb * 64 + nt * 8 + tig * 2;
                s[nt][0] = (c0     > rglob0) ? -1e30f : s[nt][0] * scale;
                s[nt][1] = (c0 + 1 > rglob0) ? -1e30f : s[nt][1] * scale;
                s[nt][2] = (c0     > rglob1) ? -1e30f : s[nt][2] * scale;
                s[nt][3] = (c0 + 1 > rglob1) ? -1e30f : s[nt][3] * scale;
            }
        } else {
#pragma unroll
            for (int nt = 0; nt < 8; nt++)
#pragma unroll
                for (int e = 0; e < 4; e++) s[nt][e] *= scale;
        }

        // ---- online softmax (warp-local: shuffle across tig lanes)
        float vm0 = -1e30f, vm1 = -1e30f;
#pragma unroll
        for (int nt = 0; nt < 8; nt++) {
            vm0 = fmaxf(vm0, fmaxf(s[nt][0], s[nt][1]));
            vm1 = fmaxf(vm1, fmaxf(s[nt][2], s[nt][3]));
        }
        vm0 = fmaxf(vm0, __shfl_xor_sync(0xffffffffu, vm0, 1));
        vm0 = fmaxf(vm0, __shfl_xor_sync(0xffffffffu, vm0, 2));
        vm1 = fmaxf(vm1, __shfl_xor_sync(0xffffffffu, vm1, 1));
        vm1 = fmaxf(vm1, __shfl_xor_sync(0xffffffffu, vm1, 2));

        float nm0 = fmaxf(mx0, vm0), nm1 = fmaxf(mx1, vm1);
        float al0 = __expf(mx0 - nm0), al1 = __expf(mx1 - nm1);

        float sum0 = 0.f, sum1 = 0.f;
#pragma unroll
        for (int nt = 0; nt < 8; nt++) {
            s[nt][0] = __expf(s[nt][0] - nm0);
            s[nt][1] = __expf(s[nt][1] - nm0);
            s[nt][2] = __expf(s[nt][2] - nm1);
            s[nt][3] = __expf(s[nt][3] - nm1);
            sum0 += s[nt][0] + s[nt][1];
            sum1 += s[nt][2] + s[nt][3];
        }
        sum0 += __shfl_xor_sync(0xffffffffu, sum0, 1);
        sum0 += __shfl_xor_sync(0xffffffffu, sum0, 2);
        sum1 += __shfl_xor_sync(0xffffffffu, sum1, 1);
        sum1 += __shfl_xor_sync(0xffffffffu, sum1, 2);

        l0 = l0 * al0 + sum0;  mx0 = nm0;
        l1 = l1 * al1 + sum1;  mx1 = nm1;

#pragma unroll
        for (int nt = 0; nt < 8; nt++) {
            o[nt][0] *= al0; o[nt][1] *= al0;
            o[nt][2] *= al1; o[nt][3] *= al1;
        }

        // ---- write P tile to smem (tf32)
        {
            const int rl0 = warp * 16 + gid;
            const int cc  = tig * 2;
#pragma unroll
            for (int nt = 0; nt < 8; nt++) {
                Ps[rl0 * PQS + nt * 8 + cc]           = f2tf(s[nt][0]);
                Ps[rl0 * PQS + nt * 8 + cc + 1]       = f2tf(s[nt][1]);
                Ps[(rl0 + 8) * PQS + nt * 8 + cc]     = f2tf(s[nt][2]);
                Ps[(rl0 + 8) * PQS + nt * 8 + cc + 1] = f2tf(s[nt][3]);
            }
        }
        __syncthreads();

        // ---- O += P @ V
        {
            const int mr = warp * 16;
#pragma unroll
            for (int kt = 0; kt < 8; kt++) {
                uint32_t af[4];
                af[0] = Ps[(mr + gid) * PQS + kt * 8 + tig];
                af[1] = Ps[(mr + gid + 8) * PQS + kt * 8 + tig];
                af[2] = Ps[(mr + gid) * PQS + kt * 8 + tig + 4];
                af[3] = Ps[(mr + gid + 8) * PQS + kt * 8 + tig + 4];
#pragma unroll
                for (int nt = 0; nt < 8; nt++) {
                    uint32_t bf[2];
                    bf[0] = Vs[(kt * 8 + tig) * KVS + nt * 8 + gid];
                    bf[1] = Vs[(kt * 8 + tig + 4) * KVS + nt * 8 + gid];
                    mma8(o[nt], af, bf);
                }
            }
        }
    }

    // ---- finalize
    const float inv0 = 1.f / l0, inv1 = 1.f / l1;
    const int yrow0 = b * TSEQ + m0g + warp * 16 + gid;
#pragma unroll
    for (int nt = 0; nt < 8; nt++) {
        int c = h * DK + nt * 8 + tig * 2;
        float2 v0 = make_float2(o[nt][0] * inv0, o[nt][1] * inv0);
        float2 v1 = make_float2(o[nt][2] * inv1, o[nt][3] * inv1);
        *(float2*)&y[(size_t)yrow0 * D_MODEL + c]       = v0;
        *(float2*)&y[(size_t)(yrow0 + 8) * D_MODEL + c] = v1;
    }
}

// ---------------------------------------------------------------------------
// launch
// ---------------------------------------------------------------------------
extern "C" void kernel_launch(void* const* d_in, const int* in_sizes, int n_in,
                              void* d_out, int out_size)
{
    const float* x      = (const float*)d_in[0];
    const float* W_attn = (const float*)d_in[1];
    const float* b_attn = (const float*)d_in[2];
    const float* W_o    = (const float*)d_in[3];
    const float* b_o    = (const float*)d_in[4];
    float* out = (float*)d_out;

    float* qkv = nullptr;
    float* yb  = nullptr;
    cudaGetSymbolAddress((void**)&qkv, g_qkv);
    cudaGetSymbolAddress((void**)&yb,  g_y);

    // 1) QKV projection: [8192,1024] @ [3072,1024]^T + b -> [8192,3072]
    sgemm_tf32_bias<<<dim3(C3 / 128, BT / 128), 256>>>(
        x, W_attn, b_attn, qkv, BT, C3, D_MODEL);

    // 2) causal flash attention -> g_y [8192,1024]
    cudaFuncSetAttribute(flash_attn_tf32,
                         cudaFuncAttributeMaxDynamicSharedMemorySize,
                         FLASH_SMEM_B);
    flash_attn_tf32<<<dim3(TSEQ / 128, BATCH * NH), 256, FLASH_SMEM_B>>>(qkv, yb);

    // 3) output projection: [8192,1024] @ [1024,1024]^T + b -> out
    sgemm_tf32_bias<<<dim3(D_MODEL / 128, BT / 128), 256>>>(
        yb, W_o, b_o, out, BT, D_MODEL, D_MODEL);
}

// round 7
// speedup vs baseline: 2.7050x; 1.2026x over previous
#include <cuda_runtime.h>
#include <math.h>
#include <stdint.h>

// Problem constants
#define D_MODEL 1024
#define NH      16
#define DK      64
#define BATCH   4
#define TSEQ    2048
#define BT      (BATCH * TSEQ)      // 8192 rows
#define C3      (3 * D_MODEL)       // 3072

// Scratch (allocation-free rule: __device__ globals)
__device__ float g_qkv[BT * C3];        // 96 MB: [8192][3072]  (Q|K|V)
__device__ float g_y[BT * D_MODEL];     // 32 MB: [8192][1024]  attention output

// ---------------------------------------------------------------------------
// helpers
// ---------------------------------------------------------------------------
__device__ __forceinline__ uint32_t f2tf(float f) {
    uint32_t r;
    asm("cvt.rna.tf32.f32 %0, %1;" : "=r"(r) : "f"(f));
    return r;
}

__device__ __forceinline__ void mma8(float c[4], const uint32_t a[4],
                                     uint32_t b0, uint32_t b1) {
    asm volatile(
        "mma.sync.aligned.m16n8k8.row.col.f32.tf32.tf32.f32 "
        "{%0,%1,%2,%3},{%4,%5,%6,%7},{%8,%9},{%0,%1,%2,%3};"
        : "+f"(c[0]), "+f"(c[1]), "+f"(c[2]), "+f"(c[3])
        : "r"(a[0]), "r"(a[1]), "r"(a[2]), "r"(a[3]), "r"(b0), "r"(b1));
}

// ldmatrix x4: 4x (8x8 b16 == 8x4 tf32) tiles. For 32-bit data, lane l of each
// matrix receives element [l>>2][l&3] -> exactly the tf32 mma fragment layout.
__device__ __forceinline__ void ldsm4(uint32_t f[4], uint32_t addr) {
    asm volatile("ldmatrix.sync.aligned.m8n8.x4.shared.b16 {%0,%1,%2,%3}, [%4];"
        : "=r"(f[0]), "=r"(f[1]), "=r"(f[2]), "=r"(f[3]) : "r"(addr));
}

__device__ __forceinline__ uint32_t smem_u32(const void* p) {
    return (uint32_t)__cvta_generic_to_shared(p);
}

// ---------------------------------------------------------------------------
// TF32 tensor-core SGEMM (NT): C[m][n] = sum_k A[m][k]*B[n][k] + bias[n]
// 128x128 tile, BK=16, 256 threads = 8 warps (2m x 4n), warp = 64x32.
// Smem layout: [128 rows][16 k], two rows packed per 128B line, 16B-group
// XOR-swizzled by line -> conflict-free STS.128 and LDSM.
// ---------------------------------------------------------------------------
__device__ __forceinline__ int swzAB(int r, int k) {
    int line = r >> 1;                                   // 128B line
    int g = (((r & 1) << 2) | (k >> 2)) ^ (line & 7);    // 16B group in line
    return line * 32 + g * 4 + (k & 3);                  // word offset
}

__global__ __launch_bounds__(256) void sgemm_tf32_bias(
    const float* __restrict__ A, const float* __restrict__ B,
    const float* __restrict__ bias, float* __restrict__ C,
    int M, int N, int K)
{
    __shared__ uint32_t As[2048];   // 128 x 16 tf32, swizzled
    __shared__ uint32_t Bs[2048];

    const int tid  = threadIdx.x;
    const int warp = tid >> 5;
    const int lane = tid & 31;
    const int gid  = lane >> 2;
    const int tig  = lane & 3;
    const int wm   = warp >> 2;   // 0..1
    const int wn   = warp & 3;    // 0..3
    const int bm   = blockIdx.y * 128;
    const int bn   = blockIdx.x * 128;

    const int lrow = tid >> 1;         // 0..127
    const int lk   = (tid & 1) * 8;    // 0 or 8

    const float* Ag = A + (size_t)(bm + lrow) * K + lk;
    const float* Bg = B + (size_t)(bn + lrow) * K + lk;

    // swizzled store offsets (words)
    const int so0 = swzAB(lrow, lk);
    const int so1 = swzAB(lrow, lk + 4);

    // ldmatrix lane mapping: lanes 0-7 -> rows r0..r0+7 @kg, 8-15 -> +8 @kg,
    // 16-23 -> r0..r0+7 @kg+1, 24-31 -> +8 @kg+1
    const int rowoff = ((lane >> 3) & 1) * 8 + (lane & 7);
    const int kxtra  = (lane >> 4) * 4;

    const uint32_t As_b = smem_u32(As);
    const uint32_t Bs_b = smem_u32(Bs);
    uint32_t aAddr[4][2], bAddr[2][2];
#pragma unroll
    for (int mt = 0; mt < 4; mt++)
#pragma unroll
        for (int ksi = 0; ksi < 2; ksi++)
            aAddr[mt][ksi] = As_b + 4 * swzAB(wm * 64 + mt * 16 + rowoff, ksi * 8 + kxtra);
#pragma unroll
    for (int ntp = 0; ntp < 2; ntp++)
#pragma unroll
        for (int ksi = 0; ksi < 2; ksi++)
            bAddr[ntp][ksi] = Bs_b + 4 * swzAB(wn * 32 + ntp * 16 + rowoff, ksi * 8 + kxtra);

    float acc[4][4][4];
#pragma unroll
    for (int i = 0; i < 4; i++)
#pragma unroll
        for (int j = 0; j < 4; j++)
#pragma unroll
            for (int e = 0; e < 4; e++) acc[i][j][e] = 0.f;

    float4 pa0 = *(const float4*)(Ag);
    float4 pa1 = *(const float4*)(Ag + 4);
    float4 pb0 = *(const float4*)(Bg);
    float4 pb1 = *(const float4*)(Bg + 4);

    for (int k0 = 0; k0 < K; k0 += 16) {
        __syncthreads();
        {
            uint4 t;
            t.x = f2tf(pa0.x); t.y = f2tf(pa0.y); t.z = f2tf(pa0.z); t.w = f2tf(pa0.w);
            *(uint4*)&As[so0] = t;
            t.x = f2tf(pa1.x); t.y = f2tf(pa1.y); t.z = f2tf(pa1.z); t.w = f2tf(pa1.w);
            *(uint4*)&As[so1] = t;
            t.x = f2tf(pb0.x); t.y = f2tf(pb0.y); t.z = f2tf(pb0.z); t.w = f2tf(pb0.w);
            *(uint4*)&Bs[so0] = t;
            t.x = f2tf(pb1.x); t.y = f2tf(pb1.y); t.z = f2tf(pb1.z); t.w = f2tf(pb1.w);
            *(uint4*)&Bs[so1] = t;
        }
        __syncthreads();

        if (k0 + 16 < K) {
            pa0 = *(const float4*)(Ag + k0 + 16);
            pa1 = *(const float4*)(Ag + k0 + 20);
            pb0 = *(const float4*)(Bg + k0 + 16);
            pb1 = *(const float4*)(Bg + k0 + 20);
        }

#pragma unroll
        for (int ksi = 0; ksi < 2; ksi++) {
            uint32_t af[4][4], bq[2][4];
#pragma unroll
            for (int mt = 0; mt < 4; mt++) ldsm4(af[mt], aAddr[mt][ksi]);
#pragma unroll
            for (int ntp = 0; ntp < 2; ntp++) ldsm4(bq[ntp], bAddr[ntp][ksi]);
            // bq[ntp]: R0=(rows n0..n0+7,kg)->nt=2ntp b0 ; R1=(+8,kg)->nt=2ntp+1 b0
            //          R2=(rows n0..n0+7,kg+1)->b1      ; R3=(+8,kg+1)->b1
#pragma unroll
            for (int mt = 0; mt < 4; mt++) {
#pragma unroll
                for (int ntp = 0; ntp < 2; ntp++) {
                    mma8(acc[mt][2 * ntp],     af[mt], bq[ntp][0], bq[ntp][2]);
                    mma8(acc[mt][2 * ntp + 1], af[mt], bq[ntp][1], bq[ntp][3]);
                }
            }
        }
    }

    // epilogue
#pragma unroll
    for (int mt = 0; mt < 4; mt++) {
        int r0 = bm + wm * 64 + mt * 16 + gid;
#pragma unroll
        for (int nt = 0; nt < 4; nt++) {
            int c = bn + wn * 32 + nt * 8 + tig * 2;
            float2 b2 = *(const float2*)&bias[c];
            float2 v0 = make_float2(acc[mt][nt][0] + b2.x, acc[mt][nt][1] + b2.y);
            float2 v1 = make_float2(acc[mt][nt][2] + b2.x, acc[mt][nt][3] + b2.y);
            *(float2*)&C[(size_t)r0 * N + c]       = v0;
            *(float2*)&C[(size_t)(r0 + 8) * N + c] = v1;
        }
    }
}

// ---------------------------------------------------------------------------
// TF32 flash attention (causal). CTA = 128 query rows of one (b,h).
// 8 warps, warp = 16 query rows x all 64 key cols -> warp-local softmax.
// Layouts (stride 68 words; 272B row pitch -> 8 LDSM rows hit distinct 16B
// groups -> conflict-free):
//   Ks [kv=64][d=64] natural ; Vs [dv=64][kv=64] transposed ; Ps [q=128][64]
// ---------------------------------------------------------------------------
#define FS2 68

#define FLASH_SMEM_U32 (2 * 64 * FS2 + 128 * FS2)
#define FLASH_SMEM_B   (FLASH_SMEM_U32 * 4)          // 69632 bytes

__global__ __launch_bounds__(256) void flash_attn_tf32(
    const float* __restrict__ qkv, float* __restrict__ y)
{
    extern __shared__ uint32_t sm[];
    uint32_t* Ks = sm;                 // [kv][d]
    uint32_t* Vs = Ks + 64 * FS2;      // [dv][kv]
    uint32_t* Ps = Vs + 64 * FS2;      // [q][kv] (also Q staging [q][d])

    const int tid  = threadIdx.x;
    const int warp = tid >> 5;
    const int lane = tid & 31;
    const int gid  = lane >> 2;
    const int tig  = lane & 3;

    const int rowoff = ((lane >> 3) & 1) * 8 + (lane & 7);
    const int kxtra  = (lane >> 4) * 4;

    const uint32_t Ks_b = smem_u32(Ks);
    const uint32_t Vs_b = smem_u32(Vs);
    const uint32_t Ps_b = smem_u32(Ps);

    const int qblk = (gridDim.x - 1) - blockIdx.x;   // big blocks first
    const int b    = blockIdx.y >> 4;
    const int h    = blockIdx.y & 15;

    const float* base = qkv + (size_t)b * TSEQ * C3 + h * DK;
    const int m0g = qblk * 128;

    // ---- stage Q into Ps natural [128][64] (each warp writes its own rows)
    {
        const int lrow = tid >> 1;
        const int lc   = (tid & 1) * 32;
        const float* qg = base + (size_t)(m0g + lrow) * C3 + lc;
#pragma unroll
        for (int u = 0; u < 32; u += 4) {
            float4 v = *(const float4*)(qg + u);
            uint4 t;
            t.x = f2tf(v.x); t.y = f2tf(v.y); t.z = f2tf(v.z); t.w = f2tf(v.w);
            *(uint4*)&Ps[lrow * FS2 + lc + u] = t;
        }
    }
    __syncwarp();

    // per-warp A-frag addresses into Ps (used for Q frags now, P frags later)
    uint32_t pAddr[8];
#pragma unroll
    for (int kt = 0; kt < 8; kt++)
        pAddr[kt] = Ps_b + 4 * ((warp * 16 + rowoff) * FS2 + kt * 8 + kxtra);

    uint32_t qf[8][4];
#pragma unroll
    for (int kt = 0; kt < 8; kt++) ldsm4(qf[kt], pAddr[kt]);

    float o[8][4];
#pragma unroll
    for (int nt = 0; nt < 8; nt++)
#pragma unroll
        for (int e = 0; e < 4; e++) o[nt][e] = 0.f;
    float mx0 = -1e30f, mx1 = -1e30f, l0 = 0.f, l1 = 0.f;

    const int rglob0 = m0g + warp * 16 + gid;
    const int rglob1 = rglob0 + 8;
    const int nkb = 2 * qblk + 2;

    const int krow = tid >> 2;          // 0..63
    const int kc   = (tid & 3) * 16;

    for (int kb = 0; kb < nkb; kb++) {
        __syncthreads();   // all warps done reading Ks/Vs from previous block

        // K natural [kv][d] (STS.128); V transposed [dv][kv] (scalar scatter)
        const float* kg = base + D_MODEL     + (size_t)(kb * 64 + krow) * C3 + kc;
        const float* vg = base + 2 * D_MODEL + (size_t)(kb * 64 + krow) * C3 + kc;
#pragma unroll
        for (int u = 0; u < 16; u += 4) {
            float4 kv4 = *(const float4*)(kg + u);
            uint4 t;
            t.x = f2tf(kv4.x); t.y = f2tf(kv4.y); t.z = f2tf(kv4.z); t.w = f2tf(kv4.w);
            *(uint4*)&Ks[krow * FS2 + kc + u] = t;
            float4 vv4 = *(const float4*)(vg + u);
            Vs[(kc + u + 0) * FS2 + krow] = f2tf(vv4.x);
            Vs[(kc + u + 1) * FS2 + krow] = f2tf(vv4.y);
            Vs[(kc + u + 2) * FS2 + krow] = f2tf(vv4.z);
            Vs[(kc + u + 3) * FS2 + krow] = f2tf(vv4.w);
        }
        __syncthreads();

        // ---- S = Q @ K^T   (warp: 16 rows x 64 cols)
        float s[8][4];
#pragma unroll
        for (int nt = 0; nt < 8; nt++)
#pragma unroll
            for (int e = 0; e < 4; e++) s[nt][e] = 0.f;

#pragma unroll
        for (int kt = 0; kt < 8; kt++) {
#pragma unroll
            for (int ntp = 0; ntp < 4; ntp++) {
                uint32_t bq[4];
                ldsm4(bq, Ks_b + 4 * ((ntp * 16 + rowoff) * FS2 + kt * 8 + kxtra));
                mma8(s[2 * ntp],     qf[kt], bq[0], bq[2]);
                mma8(s[2 * ntp + 1], qf[kt], bq[1], bq[3]);
            }
        }

        // ---- scale + causal mask
        const float scale = 0.125f;
        if (kb >= 2 * qblk) {
#pragma unroll
            for (int nt = 0; nt < 8; nt++) {
                int c0 = kb * 64 + nt * 8 + tig * 2;
                s[nt][0] = (c0     > rglob0) ? -1e30f : s[nt][0] * scale;
                s[nt][1] = (c0 + 1 > rglob0) ? -1e30f : s[nt][1] * scale;
                s[nt][2] = (c0     > rglob1) ? -1e30f : s[nt][2] * scale;
                s[nt][3] = (c0 + 1 > rglob1) ? -1e30f : s[nt][3] * scale;
            }
        } else {
#pragma unroll
            for (int nt = 0; nt < 8; nt++)
#pragma unroll
                for (int e = 0; e < 4; e++) s[nt][e] *= scale;
        }

        // ---- online softmax (warp-local: shuffle across tig lanes)
        float vm0 = -1e30f, vm1 = -1e30f;
#pragma unroll
        for (int nt = 0; nt < 8; nt++) {
            vm0 = fmaxf(vm0, fmaxf(s[nt][0], s[nt][1]));
            vm1 = fmaxf(vm1, fmaxf(s[nt][2], s[nt][3]));
        }
        vm0 = fmaxf(vm0, __shfl_xor_sync(0xffffffffu, vm0, 1));
        vm0 = fmaxf(vm0, __shfl_xor_sync(0xffffffffu, vm0, 2));
        vm1 = fmaxf(vm1, __shfl_xor_sync(0xffffffffu, vm1, 1));
        vm1 = fmaxf(vm1, __shfl_xor_sync(0xffffffffu, vm1, 2));

        float nm0 = fmaxf(mx0, vm0), nm1 = fmaxf(mx1, vm1);
        float al0 = __expf(mx0 - nm0), al1 = __expf(mx1 - nm1);

        float sum0 = 0.f, sum1 = 0.f;
#pragma unroll
        for (int nt = 0; nt < 8; nt++) {
            s[nt][0] = __expf(s[nt][0] - nm0);
            s[nt][1] = __expf(s[nt][1] - nm0);
            s[nt][2] = __expf(s[nt][2] - nm1);
            s[nt][3] = __expf(s[nt][3] - nm1);
            sum0 += s[nt][0] + s[nt][1];
            sum1 += s[nt][2] + s[nt][3];
        }
        sum0 += __shfl_xor_sync(0xffffffffu, sum0, 1);
        sum0 += __shfl_xor_sync(0xffffffffu, sum0, 2);
        sum1 += __shfl_xor_sync(0xffffffffu, sum1, 1);
        sum1 += __shfl_xor_sync(0xffffffffu, sum1, 2);

        l0 = l0 * al0 + sum0;  mx0 = nm0;
        l1 = l1 * al1 + sum1;  mx1 = nm1;

#pragma unroll
        for (int nt = 0; nt < 8; nt++) {
            o[nt][0] *= al0; o[nt][1] *= al0;
            o[nt][2] *= al1; o[nt][3] *= al1;
        }

        // ---- write P tile to smem (warp-private rows)
        {
            const int rl0 = warp * 16 + gid;
            const int cc  = tig * 2;
#pragma unroll
            for (int nt = 0; nt < 8; nt++) {
                Ps[rl0 * FS2 + nt * 8 + cc]           = f2tf(s[nt][0]);
                Ps[rl0 * FS2 + nt * 8 + cc + 1]       = f2tf(s[nt][1]);
                Ps[(rl0 + 8) * FS2 + nt * 8 + cc]     = f2tf(s[nt][2]);
                Ps[(rl0 + 8) * FS2 + nt * 8 + cc + 1] = f2tf(s[nt][3]);
            }
        }
        __syncwarp();

        // ---- O += P @ V
#pragma unroll
        for (int kt = 0; kt < 8; kt++) {
            uint32_t af[4];
            ldsm4(af, pAddr[kt]);
#pragma unroll
            for (int ntp = 0; ntp < 4; ntp++) {
                uint32_t bq[4];
                ldsm4(bq, Vs_b + 4 * ((ntp * 16 + rowoff) * FS2 + kt * 8 + kxtra));
                mma8(o[2 * ntp],     af, bq[0], bq[2]);
                mma8(o[2 * ntp + 1], af, bq[1], bq[3]);
            }
        }
    }

    // ---- finalize
    const float inv0 = 1.f / l0, inv1 = 1.f / l1;
    const int yrow0 = b * TSEQ + m0g + warp * 16 + gid;
#pragma unroll
    for (int nt = 0; nt < 8; nt++) {
        int c = h * DK + nt * 8 + tig * 2;
        float2 v0 = make_float2(o[nt][0] * inv0, o[nt][1] * inv0);
        float2 v1 = make_float2(o[nt][2] * inv1, o[nt][3] * inv1);
        *(float2*)&y[(size_t)yrow0 * D_MODEL + c]       = v0;
        *(float2*)&y[(size_t)(yrow0 + 8) * D_MODEL + c] = v1;
    }
}

// ---------------------------------------------------------------------------
// launch
// ---------------------------------------------------------------------------
extern "C" void kernel_launch(void* const* d_in, const int* in_sizes, int n_in,
                              void* d_out, int out_size)
{
    const float* x      = (const float*)d_in[0];
    const float* W_attn = (const float*)d_in[1];
    const float* b_attn = (const float*)d_in[2];
    const float* W_o    = (const float*)d_in[3];
    const float* b_o    = (const float*)d_in[4];
    float* out = (float*)d_out;

    float* qkv = nullptr;
    float* yb  = nullptr;
    cudaGetSymbolAddress((void**)&qkv, g_qkv);
    cudaGetSymbolAddress((void**)&yb,  g_y);

    // 1) QKV projection: [8192,1024] @ [3072,1024]^T + b -> [8192,3072]
    sgemm_tf32_bias<<<dim3(C3 / 128, BT / 128), 256>>>(
        x, W_attn, b_attn, qkv, BT, C3, D_MODEL);

    // 2) causal flash attention -> g_y [8192,1024]
    cudaFuncSetAttribute(flash_attn_tf32,
                         cudaFuncAttributeMaxDynamicSharedMemorySize,
                         FLASH_SMEM_B);
    flash_attn_tf32<<<dim3(TSEQ / 128, BATCH * NH), 256, FLASH_SMEM_B>>>(qkv, yb);

    // 3) output projection: [8192,1024] @ [1024,1024]^T + b -> out
    sgemm_tf32_bias<<<dim3(D_MODEL / 128, BT / 128), 256>>>(
        yb, W_o, b_o, out, BT, D_MODEL, D_MODEL);
}

// round 9
// speedup vs baseline: 3.8012x; 1.4052x over previous
#include <cuda_runtime.h>
#include <cuda_fp16.h>
#include <math.h>
#include <stdint.h>

// Problem constants
#define D_MODEL 1024
#define NH      16
#define DK      64
#define BATCH   4
#define TSEQ    2048
#define BT      (BATCH * TSEQ)      // 8192 rows
#define C3      (3 * D_MODEL)       // 3072

// Scratch (allocation-free rule: __device__ globals)
__device__ float g_qkv[BT * C3];        // 96 MB [8192][3072]
__device__ float g_y[BT * D_MODEL];     // 32 MB [8192][1024]

// ---------------------------------------------------------------------------
// helpers
// ---------------------------------------------------------------------------
// pack two floats into half2 word: lo -> bits[0:16), hi -> bits[16:32)
__device__ __forceinline__ uint32_t h2(float lo, float hi) {
    uint32_t r;
    asm("cvt.rn.f16x2.f32 %0, %1, %2;" : "=r"(r) : "f"(hi), "f"(lo));
    return r;
}

__device__ __forceinline__ void mmah(float c[4], const uint32_t a[4],
                                     uint32_t b0, uint32_t b1) {
    asm volatile(
        "mma.sync.aligned.m16n8k16.row.col.f32.f16.f16.f32 "
        "{%0,%1,%2,%3},{%4,%5,%6,%7},{%8,%9},{%0,%1,%2,%3};"
        : "+f"(c[0]), "+f"(c[1]), "+f"(c[2]), "+f"(c[3])
        : "r"(a[0]), "r"(a[1]), "r"(a[2]), "r"(a[3]), "r"(b0), "r"(b1));
}

__device__ __forceinline__ void ldsm4(uint32_t f[4], uint32_t addr) {
    asm volatile("ldmatrix.sync.aligned.m8n8.x4.shared.b16 {%0,%1,%2,%3}, [%4];"
        : "=r"(f[0]), "=r"(f[1]), "=r"(f[2]), "=r"(f[3]) : "r"(addr));
}

__device__ __forceinline__ void ldsm4t(uint32_t f[4], uint32_t addr) {
    asm volatile("ldmatrix.sync.aligned.m8n8.x4.trans.shared.b16 {%0,%1,%2,%3}, [%4];"
        : "=r"(f[0]), "=r"(f[1]), "=r"(f[2]), "=r"(f[3]) : "r"(addr));
}

__device__ __forceinline__ uint32_t smem_u32(const void* p) {
    return (uint32_t)__cvta_generic_to_shared(p);
}

// ---------------------------------------------------------------------------
// FP16 tensor-core GEMM (NT): C[m][n] = sum_k A[m][k]*B[n][k] + bias[n]
// fp32 in/out, fp16 fragments, fp32 accumulate.
// 128x128 tile, BK=32, 256 threads = 8 warps (2m x 4n), warp = 64x32.
// Smem rows: 32 halves (16 words) + pad -> stride 20 words (80 B);
// 5r mod 8 distinct -> LDSM conflict-free.
// ---------------------------------------------------------------------------
#define GS 20   // row stride in words

__global__ __launch_bounds__(256) void gemm_f16_bias(
    const float* __restrict__ A, const float* __restrict__ B,
    const float* __restrict__ bias, float* __restrict__ C,
    int M, int N, int K)
{
    __shared__ uint32_t As[128 * GS];
    __shared__ uint32_t Bs[128 * GS];

    const int tid  = threadIdx.x;
    const int warp = tid >> 5;
    const int lane = tid & 31;
    const int gid  = lane >> 2;
    const int tig  = lane & 3;
    const int wm   = warp >> 2;   // 0..1
    const int wn   = warp & 3;    // 0..3
    const int bm   = blockIdx.y * 128;
    const int bn   = blockIdx.x * 128;

    const int lrow = tid >> 1;          // 0..127
    const int lf   = (tid & 1) * 16;    // float offset in row: 0 or 16

    const float* Ag = A + (size_t)(bm + lrow) * K + lf;
    const float* Bg = B + (size_t)(bn + lrow) * K + lf;

    const int so = lrow * GS + (tid & 1) * 8;   // word offset of thread's 8 words

    // ldmatrix lane mapping
    const int rowoff = ((lane >> 3) & 1) * 8 + (lane & 7);
    const int kxw    = (lane >> 4) * 4;          // word offset within k16 chunk

    const uint32_t As_b = smem_u32(As);
    const uint32_t Bs_b = smem_u32(Bs);
    uint32_t aAddr[4][2], bAddr[2][2];
#pragma unroll
    for (int mt = 0; mt < 4; mt++)
#pragma unroll
        for (int ks = 0; ks < 2; ks++)
            aAddr[mt][ks] = As_b + 4 * ((wm * 64 + mt * 16 + rowoff) * GS + ks * 8 + kxw);
#pragma unroll
    for (int ntp = 0; ntp < 2; ntp++)
#pragma unroll
        for (int ks = 0; ks < 2; ks++)
            bAddr[ntp][ks] = Bs_b + 4 * ((wn * 32 + ntp * 16 + rowoff) * GS + ks * 8 + kxw);

    float acc[4][4][4];
#pragma unroll
    for (int i = 0; i < 4; i++)
#pragma unroll
        for (int j = 0; j < 4; j++)
#pragma unroll
            for (int e = 0; e < 4; e++) acc[i][j][e] = 0.f;

    float4 pa[4], pb[4];
#pragma unroll
    for (int u = 0; u < 4; u++) {
        pa[u] = *(const float4*)(Ag + u * 4);
        pb[u] = *(const float4*)(Bg + u * 4);
    }

    for (int k0 = 0; k0 < K; k0 += 32) {
        __syncthreads();
        {
            uint4 t;
            t.x = h2(pa[0].x, pa[0].y); t.y = h2(pa[0].z, pa[0].w);
            t.z = h2(pa[1].x, pa[1].y); t.w = h2(pa[1].z, pa[1].w);
            *(uint4*)&As[so] = t;
            t.x = h2(pa[2].x, pa[2].y); t.y = h2(pa[2].z, pa[2].w);
            t.z = h2(pa[3].x, pa[3].y); t.w = h2(pa[3].z, pa[3].w);
            *(uint4*)&As[so + 4] = t;
            t.x = h2(pb[0].x, pb[0].y); t.y = h2(pb[0].z, pb[0].w);
            t.z = h2(pb[1].x, pb[1].y); t.w = h2(pb[1].z, pb[1].w);
            *(uint4*)&Bs[so] = t;
            t.x = h2(pb[2].x, pb[2].y); t.y = h2(pb[2].z, pb[2].w);
            t.z = h2(pb[3].x, pb[3].y); t.w = h2(pb[3].z, pb[3].w);
            *(uint4*)&Bs[so + 4] = t;
        }
        __syncthreads();

        if (k0 + 32 < K) {
#pragma unroll
            for (int u = 0; u < 4; u++) {
                pa[u] = *(const float4*)(Ag + k0 + 32 + u * 4);
                pb[u] = *(const float4*)(Bg + k0 + 32 + u * 4);
            }
        }

#pragma unroll
        for (int ks = 0; ks < 2; ks++) {
            uint32_t af[4][4], bq[2][4];
#pragma unroll
            for (int mt = 0; mt < 4; mt++) ldsm4(af[mt], aAddr[mt][ks]);
#pragma unroll
            for (int ntp = 0; ntp < 2; ntp++) ldsm4(bq[ntp], bAddr[ntp][ks]);
            // bq: M0=(nLo,kLo) M1=(nHi,kLo) M2=(nLo,kHi) M3=(nHi,kHi)
#pragma unroll
            for (int mt = 0; mt < 4; mt++)
#pragma unroll
                for (int ntp = 0; ntp < 2; ntp++) {
                    mmah(acc[mt][2 * ntp],     af[mt], bq[ntp][0], bq[ntp][2]);
                    mmah(acc[mt][2 * ntp + 1], af[mt], bq[ntp][1], bq[ntp][3]);
                }
        }
    }

    // epilogue (C frag layout of m16n8k16 == m16n8k8)
#pragma unroll
    for (int mt = 0; mt < 4; mt++) {
        int r0 = bm + wm * 64 + mt * 16 + gid;
#pragma unroll
        for (int nt = 0; nt < 4; nt++) {
            int c = bn + wn * 32 + nt * 8 + tig * 2;
            float2 b2 = *(const float2*)&bias[c];
            float2 v0 = make_float2(acc[mt][nt][0] + b2.x, acc[mt][nt][1] + b2.y);
            float2 v1 = make_float2(acc[mt][nt][2] + b2.x, acc[mt][nt][3] + b2.y);
            *(float2*)&C[(size_t)r0 * N + c]       = v0;
            *(float2*)&C[(size_t)(r0 + 8) * N + c] = v1;
        }
    }
}

// ---------------------------------------------------------------------------
// FP16 flash attention (causal). CTA = 128 query rows of one (b,h).
// 8 warps, warp = 16 query rows x all 64 key cols -> warp-local softmax.
// Rows of 64 halves (32 words) + pad -> stride 36 words (144 B);
// 9r mod 8 distinct -> LDSM conflict-free. K,V stored natural [kv][.];
// V fragments via ldmatrix.trans (no scalar transpose).
// ---------------------------------------------------------------------------
#define FS3 36
#define FLASH_SMEM_U32 (2 * 64 * FS3 + 128 * FS3)
#define FLASH_SMEM_B   (FLASH_SMEM_U32 * 4)          // 36864 bytes

__global__ __launch_bounds__(256) void flash_attn_f16(
    const float* __restrict__ qkv, float* __restrict__ y)
{
    extern __shared__ uint32_t sm[];
    uint32_t* Ks = sm;                 // [kv=64][d=64] halves
    uint32_t* Vs = Ks + 64 * FS3;      // [kv=64][dv=64] halves (natural)
    uint32_t* Ps = Vs + 64 * FS3;      // [q=128][kv=64] halves (also Q staging)

    const int tid  = threadIdx.x;
    const int warp = tid >> 5;
    const int lane = tid & 31;
    const int gid  = lane >> 2;
    const int tig  = lane & 3;

    const int rowoff = ((lane >> 3) & 1) * 8 + (lane & 7);
    const int kxw    = (lane >> 4) * 4;

    const uint32_t Ks_b = smem_u32(Ks);
    const uint32_t Vs_b = smem_u32(Vs);
    const uint32_t Ps_b = smem_u32(Ps);

    const int qblk = (gridDim.x - 1) - blockIdx.x;   // big blocks first
    const int b    = blockIdx.y >> 4;
    const int h    = blockIdx.y & 15;

    const float* base = qkv + (size_t)b * TSEQ * C3 + h * DK;
    const int m0g = qblk * 128;

    // ---- stage Q into Ps [128][64] halves (warp-private rows)
    {
        const int lrow = tid >> 1;
        const int lc   = (tid & 1) * 32;             // float (=half) offset
        const float* qg = base + (size_t)(m0g + lrow) * C3 + lc;
        uint32_t* dst = &Ps[lrow * FS3 + (tid & 1) * 16];
#pragma unroll
        for (int u = 0; u < 4; u++) {
            float4 v0 = *(const float4*)(qg + u * 8);
            float4 v1 = *(const float4*)(qg + u * 8 + 4);
            uint4 t;
            t.x = h2(v0.x, v0.y); t.y = h2(v0.z, v0.w);
            t.z = h2(v1.x, v1.y); t.w = h2(v1.z, v1.w);
            *(uint4*)(dst + u * 4) = t;
        }
    }
    __syncwarp();

    // per-warp A-frag addresses into Ps (Q frags now, P frags later)
    uint32_t pAddr[4];
#pragma unroll
    for (int kt = 0; kt < 4; kt++)
        pAddr[kt] = Ps_b + 4 * ((warp * 16 + rowoff) * FS3 + kt * 8 + kxw);

    uint32_t qf[4][4];
#pragma unroll
    for (int kt = 0; kt < 4; kt++) ldsm4(qf[kt], pAddr[kt]);

    float o[8][4];
#pragma unroll
    for (int nt = 0; nt < 8; nt++)
#pragma unroll
        for (int e = 0; e < 4; e++) o[nt][e] = 0.f;
    float mx0 = -1e30f, mx1 = -1e30f, l0 = 0.f, l1 = 0.f;

    const int rglob0 = m0g + warp * 16 + gid;
    const int rglob1 = rglob0 + 8;
    const int nkb = 2 * qblk + 2;

    const int krow = tid >> 2;          // 0..63
    const int kc   = (tid & 3) * 16;    // half offset in row

    for (int kb = 0; kb < nkb; kb++) {
        __syncthreads();   // all warps done reading Ks/Vs from previous block

        const float* kg = base + D_MODEL     + (size_t)(kb * 64 + krow) * C3 + kc;
        const float* vg = base + 2 * D_MODEL + (size_t)(kb * 64 + krow) * C3 + kc;
        {
            uint32_t* kd = &Ks[krow * FS3 + (kc >> 1)];
            uint32_t* vd = &Vs[krow * FS3 + (kc >> 1)];
#pragma unroll
            for (int u = 0; u < 2; u++) {
                float4 a0 = *(const float4*)(kg + u * 8);
                float4 a1 = *(const float4*)(kg + u * 8 + 4);
                uint4 t;
                t.x = h2(a0.x, a0.y); t.y = h2(a0.z, a0.w);
                t.z = h2(a1.x, a1.y); t.w = h2(a1.z, a1.w);
                *(uint4*)(kd + u * 4) = t;
                float4 b0 = *(const float4*)(vg + u * 8);
                float4 b1 = *(const float4*)(vg + u * 8 + 4);
                t.x = h2(b0.x, b0.y); t.y = h2(b0.z, b0.w);
                t.z = h2(b1.x, b1.y); t.w = h2(b1.z, b1.w);
                *(uint4*)(vd + u * 4) = t;
            }
        }
        __syncthreads();

        // ---- S = Q @ K^T   (warp: 16 rows x 64 cols; 16 mma.k16)
        float s[8][4];
#pragma unroll
        for (int nt = 0; nt < 8; nt++)
#pragma unroll
            for (int e = 0; e < 4; e++) s[nt][e] = 0.f;

#pragma unroll
        for (int kt = 0; kt < 4; kt++) {
#pragma unroll
            for (int ntp = 0; ntp < 4; ntp++) {
                uint32_t bq[4];
                ldsm4(bq, Ks_b + 4 * ((ntp * 16 + rowoff) * FS3 + kt * 8 + kxw));
                mmah(s[2 * ntp],     qf[kt], bq[0], bq[2]);
                mmah(s[2 * ntp + 1], qf[kt], bq[1], bq[3]);
            }
        }

        // ---- scale + causal mask
        const float scale = 0.125f;
        if (kb >= 2 * qblk) {
#pragma unroll
            for (int nt = 0; nt < 8; nt++) {
                int c0 = kb * 64 + nt * 8 + tig * 2;
                s[nt][0] = (c0     > rglob0) ? -1e30f : s[nt][0] * scale;
                s[nt][1] = (c0 + 1 > rglob0) ? -1e30f : s[nt][1] * scale;
                s[nt][2] = (c0     > rglob1) ? -1e30f : s[nt][2] * scale;
                s[nt][3] = (c0 + 1 > rglob1) ? -1e30f : s[nt][3] * scale;
            }
        } else {
#pragma unroll
            for (int nt = 0; nt < 8; nt++)
#pragma unroll
                for (int e = 0; e < 4; e++) s[nt][e] *= scale;
        }

        // ---- online softmax (warp-local: shuffle across tig lanes)
        float vm0 = -1e30f, vm1 = -1e30f;
#pragma unroll
        for (int nt = 0; nt < 8; nt++) {
            vm0 = fmaxf(vm0, fmaxf(s[nt][0], s[nt][1]));
            vm1 = fmaxf(vm1, fmaxf(s[nt][2], s[nt][3]));
        }
        vm0 = fmaxf(vm0, __shfl_xor_sync(0xffffffffu, vm0, 1));
        vm0 = fmaxf(vm0, __shfl_xor_sync(0xffffffffu, vm0, 2));
        vm1 = fmaxf(vm1, __shfl_xor_sync(0xffffffffu, vm1, 1));
        vm1 = fmaxf(vm1, __shfl_xor_sync(0xffffffffu, vm1, 2));

        float nm0 = fmaxf(mx0, vm0), nm1 = fmaxf(mx1, vm1);
        float al0 = __expf(mx0 - nm0), al1 = __expf(mx1 - nm1);

        float sum0 = 0.f, sum1 = 0.f;
#pragma unroll
        for (int nt = 0; nt < 8; nt++) {
            s[nt][0] = __expf(s[nt][0] - nm0);
            s[nt][1] = __expf(s[nt][1] - nm0);
            s[nt][2] = __expf(s[nt][2] - nm1);
            s[nt][3] = __expf(s[nt][3] - nm1);
            sum0 += s[nt][0] + s[nt][1];
            sum1 += s[nt][2] + s[nt][3];
        }
        sum0 += __shfl_xor_sync(0xffffffffu, sum0, 1);
        sum0 += __shfl_xor_sync(0xffffffffu, sum0, 2);
        sum1 += __shfl_xor_sync(0xffffffffu, sum1, 1);
        sum1 += __shfl_xor_sync(0xffffffffu, sum1, 2);

        l0 = l0 * al0 + sum0;  mx0 = nm0;
        l1 = l1 * al1 + sum1;  mx1 = nm1;

#pragma unroll
        for (int nt = 0; nt < 8; nt++) {
            o[nt][0] *= al0; o[nt][1] *= al0;
            o[nt][2] *= al1; o[nt][3] *= al1;
        }

        // ---- write P tile as half2 (warp-private rows; conflict-free)
        {
            const int rl0 = warp * 16 + gid;
#pragma unroll
            for (int nt = 0; nt < 8; nt++) {
                Ps[rl0 * FS3 + nt * 4 + tig]       = h2(s[nt][0], s[nt][1]);
                Ps[(rl0 + 8) * FS3 + nt * 4 + tig] = h2(s[nt][2], s[nt][3]);
            }
        }
        __syncwarp();

        // ---- O += P @ V  (V via trans-LDSM: M0=(kLo,nLo) M1=(kHi,nLo)
        //                   M2=(kLo,nHi) M3=(kHi,nHi))
#pragma unroll
        for (int kt = 0; kt < 4; kt++) {
            uint32_t af[4];
            ldsm4(af, pAddr[kt]);
#pragma unroll
            for (int ntp = 0; ntp < 4; ntp++) {
                uint32_t bq[4];
                ldsm4t(bq, Vs_b + 4 * ((kt * 16 + rowoff) * FS3 + ntp * 8 + kxw));
                mmah(o[2 * ntp],     af, bq[0], bq[1]);
                mmah(o[2 * ntp + 1], af, bq[2], bq[3]);
            }
        }
    }

    // ---- finalize
    const float inv0 = 1.f / l0, inv1 = 1.f / l1;
    const int yrow0 = b * TSEQ + m0g + warp * 16 + gid;
#pragma unroll
    for (int nt = 0; nt < 8; nt++) {
        int c = h * DK + nt * 8 + tig * 2;
        float2 v0 = make_float2(o[nt][0] * inv0, o[nt][1] * inv0);
        float2 v1 = make_float2(o[nt][2] * inv1, o[nt][3] * inv1);
        *(float2*)&y[(size_t)yrow0 * D_MODEL + c]       = v0;
        *(float2*)&y[(size_t)(yrow0 + 8) * D_MODEL + c] = v1;
    }
}

// ---------------------------------------------------------------------------
// launch
// ---------------------------------------------------------------------------
extern "C" void kernel_launch(void* const* d_in, const int* in_sizes, int n_in,
                              void* d_out, int out_size)
{
    const float* x      = (const float*)d_in[0];
    const float* W_attn = (const float*)d_in[1];
    const float* b_attn = (const float*)d_in[2];
    const float* W_o    = (const float*)d_in[3];
    const float* b_o    = (const float*)d_in[4];
    float* out = (float*)d_out;

    float *qkv = nullptr, *yb = nullptr;
    cudaGetSymbolAddress((void**)&qkv, g_qkv);
    cudaGetSymbolAddress((void**)&yb,  g_y);

    // 1) QKV projection: [8192,1024] @ [3072,1024]^T + b -> [8192,3072]
    gemm_f16_bias<<<dim3(C3 / 128, BT / 128), 256>>>(
        x, W_attn, b_attn, qkv, BT, C3, D_MODEL);

    // 2) causal flash attention -> g_y [8192,1024]
    cudaFuncSetAttribute(flash_attn_f16,
                         cudaFuncAttributeMaxDynamicSharedMemorySize,
                         FLASH_SMEM_B);
    flash_attn_f16<<<dim3(TSEQ / 128, BATCH * NH), 256, FLASH_SMEM_B>>>(qkv, yb);

    // 3) output projection: [8192,1024] @ [1024,1024]^T + b -> out
    gemm_f16_bias<<<dim3(D_MODEL / 128, BT / 128), 256>>>(
        yb, W_o, b_o, out, BT, D_MODEL, D_MODEL);
}

// round 10
// speedup vs baseline: 5.7050x; 1.5008x over previous
#include <cuda_runtime.h>
#include <cuda_fp16.h>
#include <math.h>
#include <stdint.h>

// Problem constants
#define D_MODEL 1024
#define NH      16
#define DK      64
#define BATCH   4
#define TSEQ    2048
#define BT      (BATCH * TSEQ)      // 8192 rows
#define C3      (3 * D_MODEL)       // 3072

// Scratch (allocation-free rule: __device__ globals), all fp16
__device__ __half g_hx[BT * D_MODEL];        // 16 MB  x
__device__ __half g_hw[C3 * D_MODEL];        //  6 MB  W_attn
__device__ __half g_hwo[D_MODEL * D_MODEL];  //  2 MB  W_o
__device__ __half g_qkv[BT * C3];            // 48 MB  QKV
__device__ __half g_hy[BT * D_MODEL];        // 16 MB  attention out

// ---------------------------------------------------------------------------
// helpers
// ---------------------------------------------------------------------------
__device__ __forceinline__ uint32_t h2(float lo, float hi) {
    uint32_t r;
    asm("cvt.rn.f16x2.f32 %0, %1, %2;" : "=r"(r) : "f"(hi), "f"(lo));
    return r;
}

__device__ __forceinline__ void mmah(float c[4], const uint32_t a[4],
                                     uint32_t b0, uint32_t b1) {
    asm volatile(
        "mma.sync.aligned.m16n8k16.row.col.f32.f16.f16.f32 "
        "{%0,%1,%2,%3},{%4,%5,%6,%7},{%8,%9},{%0,%1,%2,%3};"
        : "+f"(c[0]), "+f"(c[1]), "+f"(c[2]), "+f"(c[3])
        : "r"(a[0]), "r"(a[1]), "r"(a[2]), "r"(a[3]), "r"(b0), "r"(b1));
}

__device__ __forceinline__ void ldsm4(uint32_t f[4], uint32_t addr) {
    asm volatile("ldmatrix.sync.aligned.m8n8.x4.shared.b16 {%0,%1,%2,%3}, [%4];"
        : "=r"(f[0]), "=r"(f[1]), "=r"(f[2]), "=r"(f[3]) : "r"(addr));
}

__device__ __forceinline__ void ldsm4t(uint32_t f[4], uint32_t addr) {
    asm volatile("ldmatrix.sync.aligned.m8n8.x4.trans.shared.b16 {%0,%1,%2,%3}, [%4];"
        : "=r"(f[0]), "=r"(f[1]), "=r"(f[2]), "=r"(f[3]) : "r"(addr));
}

__device__ __forceinline__ uint32_t smem_u32(const void* p) {
    return (uint32_t)__cvta_generic_to_shared(p);
}

__device__ __forceinline__ void cp16(uint32_t dst, const void* src) {
    asm volatile("cp.async.cg.shared.global [%0], [%1], 16;"
                 :: "r"(dst), "l"(src) : "memory");
}
#define CP_COMMIT() asm volatile("cp.async.commit_group;" ::: "memory")
#define CP_WAIT(n)  asm volatile("cp.async.wait_group %0;" :: "n"(n) : "memory")

// ---------------------------------------------------------------------------
// fp32 -> fp16 convert (8 elems/thread)
// ---------------------------------------------------------------------------
__global__ __launch_bounds__(256) void f2h(
    const float* __restrict__ in, __half* __restrict__ out, int n)
{
    int i = (blockIdx.x * 256 + threadIdx.x) * 8;
    if (i < n) {
        float4 a = *(const float4*)(in + i);
        float4 b = *(const float4*)(in + i + 4);
        uint4 t;
        t.x = h2(a.x, a.y); t.y = h2(a.z, a.w);
        t.z = h2(b.x, b.y); t.w = h2(b.z, b.w);
        *(uint4*)(out + i) = t;
    }
}

// ---------------------------------------------------------------------------
// FP16 tensor-core GEMM (NT): C[m][n] = sum_k A[m][k]*B[n][k] + bias[n]
// A,B fp16; out fp16 (OUTH) or fp32. 128x128 tile, BK=32, 8 warps (2m x 4n).
// 3-stage cp.async pipeline, rows stride 20 words (5r mod 8 -> LDSM clean).
// ---------------------------------------------------------------------------
#define GS 20
#define GMW (128 * GS)              // words per matrix per stage (2560)
#define GSTG (2 * GMW)              // words per stage (A+B)
#define GEMM_SMEM_B (3 * GSTG * 4)  // 61440 bytes

template<bool OUTH>
__global__ __launch_bounds__(256) void gemm_f16(
    const __half* __restrict__ A, const __half* __restrict__ B,
    const float* __restrict__ bias, void* __restrict__ Cout,
    int M, int N, int K)
{
    extern __shared__ uint32_t gsm[];
    const uint32_t smb = smem_u32(gsm);

    const int tid  = threadIdx.x;
    const int warp = tid >> 5;
    const int lane = tid & 31;
    const int gid  = lane >> 2;
    const int tig  = lane & 3;
    const int wm   = warp >> 2;   // 0..1
    const int wn   = warp & 3;    // 0..3
    const int bm   = blockIdx.y * 128;
    const int bn   = blockIdx.x * 128;

    // loader: per matrix 512 x 16B chunks; thread covers rows lr0, lr0+64 @ j
    const int lr0 = tid >> 2;          // 0..63
    const int lj  = tid & 3;           // 16B chunk in row
    const __half* Ag0 = A + (size_t)(bm + lr0) * K + lj * 8;
    const __half* Ag1 = A + (size_t)(bm + lr0 + 64) * K + lj * 8;
    const __half* Bg0 = B + (size_t)(bn + lr0) * K + lj * 8;
    const __half* Bg1 = B + (size_t)(bn + lr0 + 64) * K + lj * 8;
    const uint32_t d0 = (lr0 * GS + lj * 4) * 4;
    const uint32_t d1 = ((lr0 + 64) * GS + lj * 4) * 4;

#define GLOAD(c, s) do {                                                     \
    uint32_t ab = smb + (uint32_t)((s) * GSTG) * 4;                          \
    uint32_t bb = ab + (uint32_t)GMW * 4;                                    \
    size_t ko = (size_t)(c) * 32;                                            \
    cp16(ab + d0, Ag0 + ko); cp16(ab + d1, Ag1 + ko);                        \
    cp16(bb + d0, Bg0 + ko); cp16(bb + d1, Bg1 + ko);                        \
    CP_COMMIT(); } while (0)

    // ldmatrix lane mapping
    const int rowoff = ((lane >> 3) & 1) * 8 + (lane & 7);
    const int kxw    = (lane >> 4) * 4;

    uint32_t aRel[4][2], bRel[2][2];
#pragma unroll
    for (int mt = 0; mt < 4; mt++)
#pragma unroll
        for (int ks = 0; ks < 2; ks++)
            aRel[mt][ks] = ((wm * 64 + mt * 16 + rowoff) * GS + ks * 8 + kxw) * 4;
#pragma unroll
    for (int ntp = 0; ntp < 2; ntp++)
#pragma unroll
        for (int ks = 0; ks < 2; ks++)
            bRel[ntp][ks] = (GMW + (wn * 32 + ntp * 16 + rowoff) * GS + ks * 8 + kxw) * 4;

    float acc[4][4][4];
#pragma unroll
    for (int i = 0; i < 4; i++)
#pragma unroll
        for (int j = 0; j < 4; j++)
#pragma unroll
            for (int e = 0; e < 4; e++) acc[i][j][e] = 0.f;

    const int nch = K >> 5;   // 32
    GLOAD(0, 0);
    GLOAD(1, 1);

    for (int c = 0; c < nch; c++) {
        const int s = c % 3;
        if (c + 1 < nch) CP_WAIT(1);
        else             CP_WAIT(0);
        __syncthreads();   // stage c visible; all warps done with stage c-1
        if (c + 2 < nch) GLOAD(c + 2, (c + 2) % 3);

        const uint32_t sb = smb + (uint32_t)(s * GSTG) * 4;
#pragma unroll
        for (int ks = 0; ks < 2; ks++) {
            uint32_t af[4][4], bq[2][4];
#pragma unroll
            for (int mt = 0; mt < 4; mt++) ldsm4(af[mt], sb + aRel[mt][ks]);
#pragma unroll
            for (int ntp = 0; ntp < 2; ntp++) ldsm4(bq[ntp], sb + bRel[ntp][ks]);
#pragma unroll
            for (int mt = 0; mt < 4; mt++)
#pragma unroll
                for (int ntp = 0; ntp < 2; ntp++) {
                    mmah(acc[mt][2 * ntp],     af[mt], bq[ntp][0], bq[ntp][2]);
                    mmah(acc[mt][2 * ntp + 1], af[mt], bq[ntp][1], bq[ntp][3]);
                }
        }
    }
#undef GLOAD

    // epilogue
#pragma unroll
    for (int mt = 0; mt < 4; mt++) {
        int r0 = bm + wm * 64 + mt * 16 + gid;
#pragma unroll
        for (int nt = 0; nt < 4; nt++) {
            int c = bn + wn * 32 + nt * 8 + tig * 2;
            float2 b2 = *(const float2*)&bias[c];
            float vx0 = acc[mt][nt][0] + b2.x, vy0 = acc[mt][nt][1] + b2.y;
            float vx1 = acc[mt][nt][2] + b2.x, vy1 = acc[mt][nt][3] + b2.y;
            if (OUTH) {
                __half* Ch = (__half*)Cout;
                *(uint32_t*)&Ch[(size_t)r0 * N + c]       = h2(vx0, vy0);
                *(uint32_t*)&Ch[(size_t)(r0 + 8) * N + c] = h2(vx1, vy1);
            } else {
                float* Cf = (float*)Cout;
                *(float2*)&Cf[(size_t)r0 * N + c]       = make_float2(vx0, vy0);
                *(float2*)&Cf[(size_t)(r0 + 8) * N + c] = make_float2(vx1, vy1);
            }
        }
    }
}

// ---------------------------------------------------------------------------
// FP16 flash attention (causal), fp16 qkv in / fp16 y out.
// CTA = 128 query rows of one (b,h); warp = 16 rows -> warp-local softmax.
// K/V double-buffered via cp.async; Q staged via cp.async.
// Rows stride 36 words (9r mod 8 -> LDSM clean).
// ---------------------------------------------------------------------------
#define FS3 36
#define PS_W (128 * FS3)           // 4608 words
#define KV_W (64 * FS3)            // 2304 words
#define FL_SMEM_B ((PS_W + 4 * KV_W) * 4)   // 55296 bytes

__global__ __launch_bounds__(256) void flash_attn_f16(
    const __half* __restrict__ qkv, __half* __restrict__ y)
{
    extern __shared__ uint32_t sm[];
    uint32_t* Ps = sm;   // [q=128][64 halves] (Q staging, then P)

    const int tid  = threadIdx.x;
    const int warp = tid >> 5;
    const int lane = tid & 31;
    const int gid  = lane >> 2;
    const int tig  = lane & 3;

    const int rowoff = ((lane >> 3) & 1) * 8 + (lane & 7);
    const int kxw    = (lane >> 4) * 4;

    const uint32_t smb  = smem_u32(sm);
    const uint32_t kvb0 = smb + (uint32_t)PS_W * 4;

    const int qblk = (gridDim.x - 1) - blockIdx.x;   // big blocks first
    const int b    = blockIdx.y >> 4;
    const int h    = blockIdx.y & 15;

    const __half* base  = qkv + (size_t)b * TSEQ * C3 + h * DK;
    const int m0g = qblk * 128;
    const __half* baseQ = base + (size_t)m0g * C3;
    const __half* baseK = base + D_MODEL;
    const __half* baseV = base + 2 * D_MODEL;

    // loader indices: rows of 64 halves = 8 x 16B chunks
    const int fr0 = tid >> 3;    // 0..31
    const int fj  = tid & 7;
    const uint32_t kv_d0 = (fr0 * FS3 + fj * 4) * 4;
    const uint32_t kv_d1 = ((fr0 + 32) * FS3 + fj * 4) * 4;

#define KVLOAD(kb, buf) do {                                                  \
    uint32_t kd = kvb0 + (uint32_t)((buf) * 2 * KV_W) * 4;                    \
    uint32_t vd = kd + (uint32_t)KV_W * 4;                                    \
    size_t ko = (size_t)((kb) * 64) * C3;                                     \
    cp16(kd + kv_d0, baseK + ko + (size_t)fr0 * C3 + fj * 8);                 \
    cp16(kd + kv_d1, baseK + ko + (size_t)(fr0 + 32) * C3 + fj * 8);          \
    cp16(vd + kv_d0, baseV + ko + (size_t)fr0 * C3 + fj * 8);                 \
    cp16(vd + kv_d1, baseV + ko + (size_t)(fr0 + 32) * C3 + fj * 8);          \
    CP_COMMIT(); } while (0)

    // ---- stage Q (4 chunks/thread) + KV(0) in one group
#pragma unroll
    for (int i = 0; i < 4; i++) {
        int row = fr0 + 32 * i;
        cp16(smb + (uint32_t)((row * FS3 + fj * 4) * 4),
             baseQ + (size_t)row * C3 + fj * 8);
    }
    KVLOAD(0, 0);
    CP_WAIT(0);
    __syncthreads();

    // per-warp A-frag addresses into Ps (Q frags now, P frags later)
    uint32_t pAddr[4];
#pragma unroll
    for (int kt = 0; kt < 4; kt++)
        pAddr[kt] = smb + 4 * ((warp * 16 + rowoff) * FS3 + kt * 8 + kxw);

    uint32_t qf[4][4];
#pragma unroll
    for (int kt = 0; kt < 4; kt++) ldsm4(qf[kt], pAddr[kt]);

    float o[8][4];
#pragma unroll
    for (int nt = 0; nt < 8; nt++)
#pragma unroll
        for (int e = 0; e < 4; e++) o[nt][e] = 0.f;
    float mx0 = -1e30f, mx1 = -1e30f, l0 = 0.f, l1 = 0.f;

    const int rglob0 = m0g + warp * 16 + gid;
    const int rglob1 = rglob0 + 8;
    const int nkb = 2 * qblk + 2;

    for (int kb = 0; kb < nkb; kb++) {
        const int s = kb & 1;
        if (kb > 0) {
            CP_WAIT(0);        // KV(kb) (committed at kb-1) done
        }
        __syncthreads();       // visible to all; everyone done with buf 1-s
        if (kb + 1 < nkb) KVLOAD(kb + 1, 1 - s);

        const uint32_t Ks_b = kvb0 + (uint32_t)(s * 2 * KV_W) * 4;
        const uint32_t Vs_b = Ks_b + (uint32_t)KV_W * 4;

        // ---- S = Q @ K^T
        float sc[8][4];
#pragma unroll
        for (int nt = 0; nt < 8; nt++)
#pragma unroll
            for (int e = 0; e < 4; e++) sc[nt][e] = 0.f;

#pragma unroll
        for (int kt = 0; kt < 4; kt++) {
#pragma unroll
            for (int ntp = 0; ntp < 4; ntp++) {
                uint32_t bq[4];
                ldsm4(bq, Ks_b + 4 * ((ntp * 16 + rowoff) * FS3 + kt * 8 + kxw));
                mmah(sc[2 * ntp],     qf[kt], bq[0], bq[2]);
                mmah(sc[2 * ntp + 1], qf[kt], bq[1], bq[3]);
            }
        }

        // ---- scale + causal mask
        const float scale = 0.125f;
        if (kb >= 2 * qblk) {
#pragma unroll
            for (int nt = 0; nt < 8; nt++) {
                int c0 = kb * 64 + nt * 8 + tig * 2;
                sc[nt][0] = (c0     > rglob0) ? -1e30f : sc[nt][0] * scale;
                sc[nt][1] = (c0 + 1 > rglob0) ? -1e30f : sc[nt][1] * scale;
                sc[nt][2] = (c0     > rglob1) ? -1e30f : sc[nt][2] * scale;
                sc[nt][3] = (c0 + 1 > rglob1) ? -1e30f : sc[nt][3] * scale;
            }
        } else {
#pragma unroll
            for (int nt = 0; nt < 8; nt++)
#pragma unroll
                for (int e = 0; e < 4; e++) sc[nt][e] *= scale;
        }

        // ---- online softmax (warp-local)
        float vm0 = -1e30f, vm1 = -1e30f;
#pragma unroll
        for (int nt = 0; nt < 8; nt++) {
            vm0 = fmaxf(vm0, fmaxf(sc[nt][0], sc[nt][1]));
            vm1 = fmaxf(vm1, fmaxf(sc[nt][2], sc[nt][3]));
        }
        vm0 = fmaxf(vm0, __shfl_xor_sync(0xffffffffu, vm0, 1));
        vm0 = fmaxf(vm0, __shfl_xor_sync(0xffffffffu, vm0, 2));
        vm1 = fmaxf(vm1, __shfl_xor_sync(0xffffffffu, vm1, 1));
        vm1 = fmaxf(vm1, __shfl_xor_sync(0xffffffffu, vm1, 2));

        float nm0 = fmaxf(mx0, vm0), nm1 = fmaxf(mx1, vm1);
        float al0 = __expf(mx0 - nm0), al1 = __expf(mx1 - nm1);

        float sum0 = 0.f, sum1 = 0.f;
#pragma unroll
        for (int nt = 0; nt < 8; nt++) {
            sc[nt][0] = __expf(sc[nt][0] - nm0);
            sc[nt][1] = __expf(sc[nt][1] - nm0);
            sc[nt][2] = __expf(sc[nt][2] - nm1);
            sc[nt][3] = __expf(sc[nt][3] - nm1);
            sum0 += sc[nt][0] + sc[nt][1];
            sum1 += sc[nt][2] + sc[nt][3];
        }
        sum0 += __shfl_xor_sync(0xffffffffu, sum0, 1);
        sum0 += __shfl_xor_sync(0xffffffffu, sum0, 2);
        sum1 += __shfl_xor_sync(0xffffffffu, sum1, 1);
        sum1 += __shfl_xor_sync(0xffffffffu, sum1, 2);

        l0 = l0 * al0 + sum0;  mx0 = nm0;
        l1 = l1 * al1 + sum1;  mx1 = nm1;

#pragma unroll
        for (int nt = 0; nt < 8; nt++) {
            o[nt][0] *= al0; o[nt][1] *= al0;
            o[nt][2] *= al1; o[nt][3] *= al1;
        }

        // ---- write P tile as half2 (warp-private rows)
        {
            const int rl0 = warp * 16 + gid;
#pragma unroll
            for (int nt = 0; nt < 8; nt++) {
                Ps[rl0 * FS3 + nt * 4 + tig]       = h2(sc[nt][0], sc[nt][1]);
                Ps[(rl0 + 8) * FS3 + nt * 4 + tig] = h2(sc[nt][2], sc[nt][3]);
            }
        }
        __syncwarp();

        // ---- O += P @ V (V via trans-LDSM)
#pragma unroll
        for (int kt = 0; kt < 4; kt++) {
            uint32_t af[4];
            ldsm4(af, pAddr[kt]);
#pragma unroll
            for (int ntp = 0; ntp < 4; ntp++) {
                uint32_t bq[4];
                ldsm4t(bq, Vs_b + 4 * ((kt * 16 + rowoff) * FS3 + ntp * 8 + kxw));
                mmah(o[2 * ntp],     af, bq[0], bq[1]);
                mmah(o[2 * ntp + 1], af, bq[2], bq[3]);
            }
        }
    }
#undef KVLOAD

    // ---- finalize (fp16 out)
    const float inv0 = 1.f / l0, inv1 = 1.f / l1;
    const int yrow0 = b * TSEQ + m0g + warp * 16 + gid;
#pragma unroll
    for (int nt = 0; nt < 8; nt++) {
        int c = h * DK + nt * 8 + tig * 2;
        *(uint32_t*)&y[(size_t)yrow0 * D_MODEL + c] =
            h2(o[nt][0] * inv0, o[nt][1] * inv0);
        *(uint32_t*)&y[(size_t)(yrow0 + 8) * D_MODEL + c] =
            h2(o[nt][2] * inv1, o[nt][3] * inv1);
    }
}

// ---------------------------------------------------------------------------
// launch
// ---------------------------------------------------------------------------
extern "C" void kernel_launch(void* const* d_in, const int* in_sizes, int n_in,
                              void* d_out, int out_size)
{
    const float* x      = (const float*)d_in[0];
    const float* W_attn = (const float*)d_in[1];
    const float* b_attn = (const float*)d_in[2];
    const float* W_o    = (const float*)d_in[3];
    const float* b_o    = (const float*)d_in[4];
    float* out = (float*)d_out;

    __half *hx, *hw, *hwo, *hqkv, *hy;
    cudaGetSymbolAddress((void**)&hx,   g_hx);
    cudaGetSymbolAddress((void**)&hw,   g_hw);
    cudaGetSymbolAddress((void**)&hwo,  g_hwo);
    cudaGetSymbolAddress((void**)&hqkv, g_qkv);
    cudaGetSymbolAddress((void**)&hy,   g_hy);

    // 0) one-time fp32 -> fp16 converts
    f2h<<<(BT * D_MODEL) / 2048, 256>>>(x, hx, BT * D_MODEL);
    f2h<<<(C3 * D_MODEL) / 2048, 256>>>(W_attn, hw, C3 * D_MODEL);
    f2h<<<(D_MODEL * D_MODEL) / 2048, 256>>>(W_o, hwo, D_MODEL * D_MODEL);

    cudaFuncSetAttribute(gemm_f16<true>,
                         cudaFuncAttributeMaxDynamicSharedMemorySize, GEMM_SMEM_B);
    cudaFuncSetAttribute(gemm_f16<false>,
                         cudaFuncAttributeMaxDynamicSharedMemorySize, GEMM_SMEM_B);
    cudaFuncSetAttribute(flash_attn_f16,
                         cudaFuncAttributeMaxDynamicSharedMemorySize, FL_SMEM_B);

    // 1) QKV projection: [8192,1024] @ [3072,1024]^T + b -> fp16 [8192,3072]
    gemm_f16<true><<<dim3(C3 / 128, BT / 128), 256, GEMM_SMEM_B>>>(
        hx, hw, b_attn, hqkv, BT, C3, D_MODEL);

    // 2) causal flash attention -> fp16 y [8192,1024]
    flash_attn_f16<<<dim3(TSEQ / 128, BATCH * NH), 256, FL_SMEM_B>>>(hqkv, hy);

    // 3) output projection: [8192,1024] @ [1024,1024]^T + b -> fp32 out
    gemm_f16<false><<<dim3(D_MODEL / 128, BT / 128), 256, GEMM_SMEM_B>>>(
        hy, hwo, b_o, out, BT, D_MODEL, D_MODEL);
}

// round 11
// speedup vs baseline: 5.8381x; 1.0233x over previous
#include <cuda_runtime.h>
#include <cuda_fp16.h>
#include <math.h>
#include <stdint.h>

// Problem constants
#define D_MODEL 1024
#define NH      16
#define DK      64
#define BATCH   4
#define TSEQ    2048
#define BT      (BATCH * TSEQ)      // 8192 rows
#define C3      (3 * D_MODEL)       // 3072

// Scratch (allocation-free rule: __device__ globals), all fp16
__device__ __half g_hx[BT * D_MODEL];        // 16 MB  x
__device__ __half g_hw[C3 * D_MODEL];        //  6 MB  W_attn
__device__ __half g_hwo[D_MODEL * D_MODEL];  //  2 MB  W_o
__device__ __half g_qkv[BT * C3];            // 48 MB  QKV
__device__ __half g_hy[BT * D_MODEL];        // 16 MB  attention out

// ---------------------------------------------------------------------------
// helpers
// ---------------------------------------------------------------------------
__device__ __forceinline__ uint32_t h2(float lo, float hi) {
    uint32_t r;
    asm("cvt.rn.f16x2.f32 %0, %1, %2;" : "=r"(r) : "f"(hi), "f"(lo));
    return r;
}

__device__ __forceinline__ void mmah(float c[4], const uint32_t a[4],
                                     uint32_t b0, uint32_t b1) {
    asm volatile(
        "mma.sync.aligned.m16n8k16.row.col.f32.f16.f16.f32 "
        "{%0,%1,%2,%3},{%4,%5,%6,%7},{%8,%9},{%0,%1,%2,%3};"
        : "+f"(c[0]), "+f"(c[1]), "+f"(c[2]), "+f"(c[3])
        : "r"(a[0]), "r"(a[1]), "r"(a[2]), "r"(a[3]), "r"(b0), "r"(b1));
}

__device__ __forceinline__ void ldsm4(uint32_t f[4], uint32_t addr) {
    asm volatile("ldmatrix.sync.aligned.m8n8.x4.shared.b16 {%0,%1,%2,%3}, [%4];"
        : "=r"(f[0]), "=r"(f[1]), "=r"(f[2]), "=r"(f[3]) : "r"(addr));
}

__device__ __forceinline__ void ldsm4t(uint32_t f[4], uint32_t addr) {
    asm volatile("ldmatrix.sync.aligned.m8n8.x4.trans.shared.b16 {%0,%1,%2,%3}, [%4];"
        : "=r"(f[0]), "=r"(f[1]), "=r"(f[2]), "=r"(f[3]) : "r"(addr));
}

__device__ __forceinline__ uint32_t smem_u32(const void* p) {
    return (uint32_t)__cvta_generic_to_shared(p);
}

__device__ __forceinline__ void cp16(uint32_t dst, const void* src) {
    asm volatile("cp.async.cg.shared.global [%0], [%1], 16;"
                 :: "r"(dst), "l"(src) : "memory");
}
#define CP_COMMIT() asm volatile("cp.async.commit_group;" ::: "memory")
#define CP_WAIT(n)  asm volatile("cp.async.wait_group %0;" :: "n"(n) : "memory")

// ---------------------------------------------------------------------------
// fp32 -> fp16 convert (8 elems/thread)
// ---------------------------------------------------------------------------
__global__ __launch_bounds__(256) void f2h(
    const float* __restrict__ in, __half* __restrict__ out, int n)
{
    int i = (blockIdx.x * 256 + threadIdx.x) * 8;
    if (i < n) {
        float4 a = *(const float4*)(in + i);
        float4 b = *(const float4*)(in + i + 4);
        uint4 t;
        t.x = h2(a.x, a.y); t.y = h2(a.z, a.w);
        t.z = h2(b.x, b.y); t.w = h2(b.z, b.w);
        *(uint4*)(out + i) = t;
    }
}

// ---------------------------------------------------------------------------
// FP16 tensor-core GEMM (NT): C[m][n] = sum_k A[m][k]*B[n][k] + bias[n]
// A,B fp16; out fp16 (OUTH) or fp32. 128x128 tile, BK=64, 8 warps (2m x 4n).
// 2-stage cp.async double buffer; rows of 64 halves, stride 36 words
// (9r mod 8 -> LDSM conflict-free). One __syncthreads per 64 K.
// ---------------------------------------------------------------------------
#define GS2 36
#define GMW2 (128 * GS2)              // words per matrix per stage (4608)
#define GSTG2 (2 * GMW2)              // words per stage (A+B)
#define GEMM_SMEM_B (2 * GSTG2 * 4)   // 73728 bytes

template<bool OUTH>
__global__ __launch_bounds__(256, 2) void gemm_f16(
    const __half* __restrict__ A, const __half* __restrict__ B,
    const float* __restrict__ bias, void* __restrict__ Cout,
    int M, int N, int K)
{
    extern __shared__ uint32_t gsm[];
    const uint32_t smb = smem_u32(gsm);

    const int tid  = threadIdx.x;
    const int warp = tid >> 5;
    const int lane = tid & 31;
    const int gid  = lane >> 2;
    const int tig  = lane & 3;
    const int wm   = warp >> 2;   // 0..1
    const int wn   = warp & 3;    // 0..3
    const int bm   = blockIdx.y * 128;
    const int bn   = blockIdx.x * 128;

    // loader: per matrix 128 rows x 8 x 16B chunks; thread covers
    // rows lr0, lr0+64 at chunks lj2, lj2+1  (4 cp16 per matrix)
    const int lr0 = tid >> 2;           // 0..63
    const int lj2 = (tid & 3) * 2;      // chunk 0,2,4,6
    const __half* Ag0 = A + (size_t)(bm + lr0) * K + lj2 * 8;
    const __half* Ag1 = A + (size_t)(bm + lr0 + 64) * K + lj2 * 8;
    const __half* Bg0 = B + (size_t)(bn + lr0) * K + lj2 * 8;
    const __half* Bg1 = B + (size_t)(bn + lr0 + 64) * K + lj2 * 8;
    const uint32_t d00 = (lr0 * GS2 + lj2 * 4) * 4;
    const uint32_t d01 = d00 + 16;
    const uint32_t d10 = ((lr0 + 64) * GS2 + lj2 * 4) * 4;
    const uint32_t d11 = d10 + 16;

#define GLOAD(c, s) do {                                                     \
    uint32_t ab = smb + (uint32_t)((s) * GSTG2) * 4;                         \
    uint32_t bb = ab + (uint32_t)GMW2 * 4;                                   \
    size_t ko = (size_t)(c) * 64;                                            \
    cp16(ab + d00, Ag0 + ko); cp16(ab + d01, Ag0 + ko + 8);                  \
    cp16(ab + d10, Ag1 + ko); cp16(ab + d11, Ag1 + ko + 8);                  \
    cp16(bb + d00, Bg0 + ko); cp16(bb + d01, Bg0 + ko + 8);                  \
    cp16(bb + d10, Bg1 + ko); cp16(bb + d11, Bg1 + ko + 8);                  \
    CP_COMMIT(); } while (0)

    // ldmatrix lane mapping
    const int rowoff = ((lane >> 3) & 1) * 8 + (lane & 7);
    const int kxw    = (lane >> 4) * 4;

    uint32_t aBase[4], bBase[2];
#pragma unroll
    for (int mt = 0; mt < 4; mt++)
        aBase[mt] = ((wm * 64 + mt * 16 + rowoff) * GS2 + kxw) * 4;
#pragma unroll
    for (int ntp = 0; ntp < 2; ntp++)
        bBase[ntp] = (GMW2 + (wn * 32 + ntp * 16 + rowoff) * GS2 + kxw) * 4;

    float acc[4][4][4];
#pragma unroll
    for (int i = 0; i < 4; i++)
#pragma unroll
        for (int j = 0; j < 4; j++)
#pragma unroll
            for (int e = 0; e < 4; e++) acc[i][j][e] = 0.f;

    const int nch = K >> 6;   // 16
    GLOAD(0, 0);

    for (int c = 0; c < nch; c++) {
        const int s = c & 1;
        CP_WAIT(0);
        __syncthreads();   // buf s ready; all warps done with buf 1-s
        if (c + 1 < nch) GLOAD(c + 1, 1 - s);

        const uint32_t sb = smb + (uint32_t)(s * GSTG2) * 4;
#pragma unroll
        for (int ks = 0; ks < 4; ks++) {
            uint32_t af[4][4], bq[2][4];
#pragma unroll
            for (int mt = 0; mt < 4; mt++)
                ldsm4(af[mt], sb + aBase[mt] + ks * 32);
#pragma unroll
            for (int ntp = 0; ntp < 2; ntp++)
                ldsm4(bq[ntp], sb + bBase[ntp] + ks * 32);
#pragma unroll
            for (int mt = 0; mt < 4; mt++)
#pragma unroll
                for (int ntp = 0; ntp < 2; ntp++) {
                    mmah(acc[mt][2 * ntp],     af[mt], bq[ntp][0], bq[ntp][2]);
                    mmah(acc[mt][2 * ntp + 1], af[mt], bq[ntp][1], bq[ntp][3]);
                }
        }
    }
#undef GLOAD

    // epilogue
#pragma unroll
    for (int mt = 0; mt < 4; mt++) {
        int r0 = bm + wm * 64 + mt * 16 + gid;
#pragma unroll
        for (int nt = 0; nt < 4; nt++) {
            int c = bn + wn * 32 + nt * 8 + tig * 2;
            float2 b2 = *(const float2*)&bias[c];
            float vx0 = acc[mt][nt][0] + b2.x, vy0 = acc[mt][nt][1] + b2.y;
            float vx1 = acc[mt][nt][2] + b2.x, vy1 = acc[mt][nt][3] + b2.y;
            if (OUTH) {
                __half* Ch = (__half*)Cout;
                *(uint32_t*)&Ch[(size_t)r0 * N + c]       = h2(vx0, vy0);
                *(uint32_t*)&Ch[(size_t)(r0 + 8) * N + c] = h2(vx1, vy1);
            } else {
                float* Cf = (float*)Cout;
                *(float2*)&Cf[(size_t)r0 * N + c]       = make_float2(vx0, vy0);
                *(float2*)&Cf[(size_t)(r0 + 8) * N + c] = make_float2(vx1, vy1);
            }
        }
    }
}

// ---------------------------------------------------------------------------
// FP16 flash attention (causal), fp16 qkv in / fp16 y out.  (R10, proven)
// CTA = 128 query rows of one (b,h); warp = 16 rows -> warp-local softmax.
// K/V double-buffered via cp.async; rows stride 36 words.
// ---------------------------------------------------------------------------
#define FS3 36
#define PS_W (128 * FS3)           // 4608 words
#define KV_W (64 * FS3)            // 2304 words
#define FL_SMEM_B ((PS_W + 4 * KV_W) * 4)   // 55296 bytes

__global__ __launch_bounds__(256) void flash_attn_f16(
    const __half* __restrict__ qkv, __half* __restrict__ y)
{
    extern __shared__ uint32_t sm[];
    uint32_t* Ps = sm;   // [q=128][64 halves] (Q staging, then P)

    const int tid  = threadIdx.x;
    const int warp = tid >> 5;
    const int lane = tid & 31;
    const int gid  = lane >> 2;
    const int tig  = lane & 3;

    const int rowoff = ((lane >> 3) & 1) * 8 + (lane & 7);
    const int kxw    = (lane >> 4) * 4;

    const uint32_t smb  = smem_u32(sm);
    const uint32_t kvb0 = smb + (uint32_t)PS_W * 4;

    const int qblk = (gridDim.x - 1) - blockIdx.x;   // big blocks first
    const int b    = blockIdx.y >> 4;
    const int h    = blockIdx.y & 15;

    const __half* base  = qkv + (size_t)b * TSEQ * C3 + h * DK;
    const int m0g = qblk * 128;
    const __half* baseQ = base + (size_t)m0g * C3;
    const __half* baseK = base + D_MODEL;
    const __half* baseV = base + 2 * D_MODEL;

    const int fr0 = tid >> 3;    // 0..31
    const int fj  = tid & 7;
    const uint32_t kv_d0 = (fr0 * FS3 + fj * 4) * 4;
    const uint32_t kv_d1 = ((fr0 + 32) * FS3 + fj * 4) * 4;

#define KVLOAD(kb, buf) do {                                                  \
    uint32_t kd = kvb0 + (uint32_t)((buf) * 2 * KV_W) * 4;                    \
    uint32_t vd = kd + (uint32_t)KV_W * 4;                                    \
    size_t ko = (size_t)((kb) * 64) * C3;                                     \
    cp16(kd + kv_d0, baseK + ko + (size_t)fr0 * C3 + fj * 8);                 \
    cp16(kd + kv_d1, baseK + ko + (size_t)(fr0 + 32) * C3 + fj * 8);          \
    cp16(vd + kv_d0, baseV + ko + (size_t)fr0 * C3 + fj * 8);                 \
    cp16(vd + kv_d1, baseV + ko + (size_t)(fr0 + 32) * C3 + fj * 8);          \
    CP_COMMIT(); } while (0)

#pragma unroll
    for (int i = 0; i < 4; i++) {
        int row = fr0 + 32 * i;
        cp16(smb + (uint32_t)((row * FS3 + fj * 4) * 4),
             baseQ + (size_t)row * C3 + fj * 8);
    }
    KVLOAD(0, 0);
    CP_WAIT(0);
    __syncthreads();

    uint32_t pAddr[4];
#pragma unroll
    for (int kt = 0; kt < 4; kt++)
        pAddr[kt] = smb + 4 * ((warp * 16 + rowoff) * FS3 + kt * 8 + kxw);

    uint32_t qf[4][4];
#pragma unroll
    for (int kt = 0; kt < 4; kt++) ldsm4(qf[kt], pAddr[kt]);

    float o[8][4];
#pragma unroll
    for (int nt = 0; nt < 8; nt++)
#pragma unroll
        for (int e = 0; e < 4; e++) o[nt][e] = 0.f;
    float mx0 = -1e30f, mx1 = -1e30f, l0 = 0.f, l1 = 0.f;

    const int rglob0 = m0g + warp * 16 + gid;
    const int rglob1 = rglob0 + 8;
    const int nkb = 2 * qblk + 2;

    for (int kb = 0; kb < nkb; kb++) {
        const int s = kb & 1;
        if (kb > 0) CP_WAIT(0);
        __syncthreads();
        if (kb + 1 < nkb) KVLOAD(kb + 1, 1 - s);

        const uint32_t Ks_b = kvb0 + (uint32_t)(s * 2 * KV_W) * 4;
        const uint32_t Vs_b = Ks_b + (uint32_t)KV_W * 4;

        float sc[8][4];
#pragma unroll
        for (int nt = 0; nt < 8; nt++)
#pragma unroll
            for (int e = 0; e < 4; e++) sc[nt][e] = 0.f;

#pragma unroll
        for (int kt = 0; kt < 4; kt++) {
#pragma unroll
            for (int ntp = 0; ntp < 4; ntp++) {
                uint32_t bq[4];
                ldsm4(bq, Ks_b + 4 * ((ntp * 16 + rowoff) * FS3 + kt * 8 + kxw));
                mmah(sc[2 * ntp],     qf[kt], bq[0], bq[2]);
                mmah(sc[2 * ntp + 1], qf[kt], bq[1], bq[3]);
            }
        }

        const float scale = 0.125f;
        if (kb >= 2 * qblk) {
#pragma unroll
            for (int nt = 0; nt < 8; nt++) {
                int c0 = kb * 64 + nt * 8 + tig * 2;
                sc[nt][0] = (c0     > rglob0) ? -1e30f : sc[nt][0] * scale;
                sc[nt][1] = (c0 + 1 > rglob0) ? -1e30f : sc[nt][1] * scale;
                sc[nt][2] = (c0     > rglob1) ? -1e30f : sc[nt][2] * scale;
                sc[nt][3] = (c0 + 1 > rglob1) ? -1e30f : sc[nt][3] * scale;
            }
        } else {
#pragma unroll
            for (int nt = 0; nt < 8; nt++)
#pragma unroll
                for (int e = 0; e < 4; e++) sc[nt][e] *= scale;
        }

        float vm0 = -1e30f, vm1 = -1e30f;
#pragma unroll
        for (int nt = 0; nt < 8; nt++) {
            vm0 = fmaxf(vm0, fmaxf(sc[nt][0], sc[nt][1]));
            vm1 = fmaxf(vm1, fmaxf(sc[nt][2], sc[nt][3]));
        }
        vm0 = fmaxf(vm0, __shfl_xor_sync(0xffffffffu, vm0, 1));
        vm0 = fmaxf(vm0, __shfl_xor_sync(0xffffffffu, vm0, 2));
        vm1 = fmaxf(vm1, __shfl_xor_sync(0xffffffffu, vm1, 1));
        vm1 = fmaxf(vm1, __shfl_xor_sync(0xffffffffu, vm1, 2));

        float nm0 = fmaxf(mx0, vm0), nm1 = fmaxf(mx1, vm1);
        float al0 = __expf(mx0 - nm0), al1 = __expf(mx1 - nm1);

        float sum0 = 0.f, sum1 = 0.f;
#pragma unroll
        for (int nt = 0; nt < 8; nt++) {
            sc[nt][0] = __expf(sc[nt][0] - nm0);
            sc[nt][1] = __expf(sc[nt][1] - nm0);
            sc[nt][2] = __expf(sc[nt][2] - nm1);
            sc[nt][3] = __expf(sc[nt][3] - nm1);
            sum0 += sc[nt][0] + sc[nt][1];
            sum1 += sc[nt][2] + sc[nt][3];
        }
        sum0 += __shfl_xor_sync(0xffffffffu, sum0, 1);
        sum0 += __shfl_xor_sync(0xffffffffu, sum0, 2);
        sum1 += __shfl_xor_sync(0xffffffffu, sum1, 1);
        sum1 += __shfl_xor_sync(0xffffffffu, sum1, 2);

        l0 = l0 * al0 + sum0;  mx0 = nm0;
        l1 = l1 * al1 + sum1;  mx1 = nm1;

#pragma unroll
        for (int nt = 0; nt < 8; nt++) {
            o[nt][0] *= al0; o[nt][1] *= al0;
            o[nt][2] *= al1; o[nt][3] *= al1;
        }

        {
            const int rl0 = warp * 16 + gid;
#pragma unroll
            for (int nt = 0; nt < 8; nt++) {
                Ps[rl0 * FS3 + nt * 4 + tig]       = h2(sc[nt][0], sc[nt][1]);
                Ps[(rl0 + 8) * FS3 + nt * 4 + tig] = h2(sc[nt][2], sc[nt][3]);
            }
        }
        __syncwarp();

#pragma unroll
        for (int kt = 0; kt < 4; kt++) {
            uint32_t af[4];
            ldsm4(af, pAddr[kt]);
#pragma unroll
            for (int ntp = 0; ntp < 4; ntp++) {
                uint32_t bq[4];
                ldsm4t(bq, Vs_b + 4 * ((kt * 16 + rowoff) * FS3 + ntp * 8 + kxw));
                mmah(o[2 * ntp],     af, bq[0], bq[1]);
                mmah(o[2 * ntp + 1], af, bq[2], bq[3]);
            }
        }
    }
#undef KVLOAD

    const float inv0 = 1.f / l0, inv1 = 1.f / l1;
    const int yrow0 = b * TSEQ + m0g + warp * 16 + gid;
#pragma unroll
    for (int nt = 0; nt < 8; nt++) {
        int c = h * DK + nt * 8 + tig * 2;
        *(uint32_t*)&y[(size_t)yrow0 * D_MODEL + c] =
            h2(o[nt][0] * inv0, o[nt][1] * inv0);
        *(uint32_t*)&y[(size_t)(yrow0 + 8) * D_MODEL + c] =
            h2(o[nt][2] * inv1, o[nt][3] * inv1);
    }
}

// ---------------------------------------------------------------------------
// launch
// ---------------------------------------------------------------------------
extern "C" void kernel_launch(void* const* d_in, const int* in_sizes, int n_in,
                              void* d_out, int out_size)
{
    const float* x      = (const float*)d_in[0];
    const float* W_attn = (const float*)d_in[1];
    const float* b_attn = (const float*)d_in[2];
    const float* W_o    = (const float*)d_in[3];
    const float* b_o    = (const float*)d_in[4];
    float* out = (float*)d_out;

    __half *hx, *hw, *hwo, *hqkv, *hy;
    cudaGetSymbolAddress((void**)&hx,   g_hx);
    cudaGetSymbolAddress((void**)&hw,   g_hw);
    cudaGetSymbolAddress((void**)&hwo,  g_hwo);
    cudaGetSymbolAddress((void**)&hqkv, g_qkv);
    cudaGetSymbolAddress((void**)&hy,   g_hy);

    // 0) one-time fp32 -> fp16 converts
    f2h<<<(BT * D_MODEL) / 2048, 256>>>(x, hx, BT * D_MODEL);
    f2h<<<(C3 * D_MODEL) / 2048, 256>>>(W_attn, hw, C3 * D_MODEL);
    f2h<<<(D_MODEL * D_MODEL) / 2048, 256>>>(W_o, hwo, D_MODEL * D_MODEL);

    cudaFuncSetAttribute(gemm_f16<true>,
                         cudaFuncAttributeMaxDynamicSharedMemorySize, GEMM_SMEM_B);
    cudaFuncSetAttribute(gemm_f16<false>,
                         cudaFuncAttributeMaxDynamicSharedMemorySize, GEMM_SMEM_B);
    cudaFuncSetAttribute(flash_attn_f16,
                         cudaFuncAttributeMaxDynamicSharedMemorySize, FL_SMEM_B);

    // 1) QKV projection: [8192,1024] @ [3072,1024]^T + b -> fp16 [8192,3072]
    gemm_f16<true><<<dim3(C3 / 128, BT / 128), 256, GEMM_SMEM_B>>>(
        hx, hw, b_attn, hqkv, BT, C3, D_MODEL);

    // 2) causal flash attention -> fp16 y [8192,1024]
    flash_attn_f16<<<dim3(TSEQ / 128, BATCH * NH), 256, FL_SMEM_B>>>(hqkv, hy);

    // 3) output projection: [8192,1024] @ [1024,1024]^T + b -> fp32 out
    gemm_f16<false><<<dim3(D_MODEL / 128, BT / 128), 256, GEMM_SMEM_B>>>(
        hy, hwo, b_o, out, BT, D_MODEL, D_MODEL);
}